// round 12
// baseline (speedup 1.0000x reference)
#include <cuda_runtime.h>
#include <cuda_bf16.h>
#include <math.h>
#include <stdint.h>

#define N_ENTS  100000
#define N_RELS  64
#define EDIM    128
#define KNBR    32
#define BATCH   16384

// ---------------- device-global scratch ------------------------------------------
__device__ float         g_EntN[(size_t)N_ENTS * EDIM];   // maxnorm(ent) fp32
__device__ __nv_bfloat16 g_TrTb[(size_t)N_ENTS * EDIM];   // bf16(EntN @ Wr^T + b)
__device__ float         g_RelN[(size_t)N_RELS * EDIM];
__device__ __nv_bfloat16 g_X1h[(size_t)BATCH * EDIM];
__device__ __nv_bfloat16 g_X1l[(size_t)BATCH * EDIM];
__device__ __nv_bfloat16 g_X2h[(size_t)BATCH * EDIM];
__device__ __nv_bfloat16 g_X2l[(size_t)BATCH * EDIM];

// ---------------- helpers ----------------------------------------------------------
__device__ __forceinline__ uint32_t smem_u32(const void* p) {
    uint32_t a;
    asm("{ .reg .u64 t; cvta.to.shared.u64 t, %1; cvt.u32.u64 %0, t; }" : "=r"(a) : "l"(p));
    return a;
}
__device__ __forceinline__ void ldmx4(uint32_t& r0, uint32_t& r1, uint32_t& r2, uint32_t& r3,
                                      uint32_t addr) {
    asm volatile("ldmatrix.sync.aligned.m8n8.x4.shared.b16 {%0,%1,%2,%3}, [%4];"
                 : "=r"(r0), "=r"(r1), "=r"(r2), "=r"(r3) : "r"(addr));
}
__device__ __forceinline__ void mma_bf16(float* d, const uint32_t* a, const uint32_t* b) {
    asm volatile(
        "mma.sync.aligned.m16n8k16.row.col.f32.bf16.bf16.f32 "
        "{%0,%1,%2,%3}, {%4,%5,%6,%7}, {%8,%9}, {%0,%1,%2,%3};"
        : "+f"(d[0]), "+f"(d[1]), "+f"(d[2]), "+f"(d[3])
        : "r"(a[0]), "r"(a[1]), "r"(a[2]), "r"(a[3]), "r"(b[0]), "r"(b[1]));
}
__device__ __forceinline__ uint32_t pk_bf2(__nv_bfloat16 a, __nv_bfloat16 b) {
    __nv_bfloat162 t(a, b);
    return *(uint32_t*)&t;
}
__device__ __forceinline__ float tanh_hw(float x) {
    float y;
    asm("tanh.approx.f32 %0, %1;" : "=f"(y) : "f"(x));
    return y;
}
__device__ __forceinline__ void cp16(uint32_t dst, const void* src) {
    asm volatile("cp.async.cg.shared.global [%0], [%1], 16;" :: "r"(dst), "l"(src));
}
#define CP_COMMIT() asm volatile("cp.async.commit_group;" ::: "memory")
#define CP_WAIT(n)  asm volatile("cp.async.wait_group %0;" :: "n"(n) : "memory")

// padded bf16 tiles, row stride 136 elems (272 B) -> conflict-free ldmatrix
#define LDT 136
#define TILE_B  (128 * LDT * 2)   // 34816
#define HTILE_B (64  * LDT * 2)   // 17408
// TrT kernel layout
#define OFF_BIAS 0
#define OFF_AH   512
#define OFF_BH1  (512 + TILE_B)
#define SMEM_TRT (512 + 2 * TILE_B)              // 70,144 -> 2 CTAs/SM
// fused output kernel layout
#define OFF_B1   0
#define OFF_B2   256
#define OA1H     512
#define OA1L     (512 + TILE_B)
#define OA2H     (512 + 2 * TILE_B)
#define OA2L     (512 + 3 * TILE_B)
#define OW1H     (512 + 4 * TILE_B)
#define OW1L     (512 + 4 * TILE_B + HTILE_B)
#define OW2H     (512 + 4 * TILE_B + 2 * HTILE_B)
#define OW2L     (512 + 4 * TILE_B + 3 * HTILE_B)
#define SMEM_OUT (512 + 4 * TILE_B + 4 * HTILE_B)   // 209,408 -> 1 CTA/SM

// async bf16 tile copy: gmem (stride 128) -> padded smem, 128 rows
__device__ __forceinline__ void copy128_async(const __nv_bfloat16* __restrict__ src,
                                              uint32_t smb, int off, int tid) {
    #pragma unroll
    for (int i = 0; i < 8; i++) {
        int g = tid + i * 256;
        int row = g >> 4, c8 = g & 15;
        cp16(smb + off + row * LDT * 2 + c8 * 16, src + (size_t)row * EDIM + c8 * 8);
    }
}
// fp32 -> bf16 hi/lo split, 64 rows
__device__ __forceinline__ void load_split64(const float* __restrict__ src,
                                             char* sm, int off_h, int off_l, int tid) {
    #pragma unroll
    for (int i = 0; i < 4; i++) {
        int g = tid + i * 256;
        int row = g >> 4, c8 = g & 15, col0 = c8 * 8;
        const float4* p = (const float4*)src + (size_t)row * 32 + c8 * 2;
        float4 v0 = p[0], v1 = p[1];
        float f[8] = {v0.x, v0.y, v0.z, v0.w, v1.x, v1.y, v1.z, v1.w};
        __nv_bfloat16 h[8], l[8];
        #pragma unroll
        for (int j = 0; j < 8; j++) {
            h[j] = __float2bfloat16(f[j]);
            l[j] = __float2bfloat16(f[j] - __bfloat162float(h[j]));
        }
        uint4 hv = make_uint4(pk_bf2(h[0], h[1]), pk_bf2(h[2], h[3]),
                              pk_bf2(h[4], h[5]), pk_bf2(h[6], h[7]));
        uint4 lv = make_uint4(pk_bf2(l[0], l[1]), pk_bf2(l[2], l[3]),
                              pk_bf2(l[4], l[5]), pk_bf2(l[6], l[7]));
        size_t o = (size_t)row * LDT * 2 + col0 * 2;
        *(uint4*)(sm + off_h + o) = hv;
        *(uint4*)(sm + off_l + o) = lv;
    }
}
// hi-only fp32->bf16, 128 rows
__device__ __forceinline__ void load_hi(const float* __restrict__ src,
                                        char* sm, int off_h, int tid) {
    #pragma unroll
    for (int i = 0; i < 8; i++) {
        int g = tid + i * 256;
        int row = g >> 4, c8 = g & 15, col0 = c8 * 8;
        const float4* p = (const float4*)src + (size_t)row * 32 + c8 * 2;
        float4 v0 = p[0], v1 = p[1];
        float f[8] = {v0.x, v0.y, v0.z, v0.w, v1.x, v1.y, v1.z, v1.w};
        __nv_bfloat16 h[8];
        #pragma unroll
        for (int j = 0; j < 8; j++) h[j] = __float2bfloat16(f[j]);
        uint4 hv = make_uint4(pk_bf2(h[0], h[1]), pk_bf2(h[2], h[3]),
                              pk_bf2(h[4], h[5]), pk_bf2(h[6], h[7]));
        *(uint4*)(sm + off_h + (size_t)row * LDT * 2 + col0 * 2) = hv;
    }
}

// ---------- fused maxnorm + single-pass bf16 GEMM -> TrTb + EntN (proven) ------------
__global__ __launch_bounds__(256, 2) void k_trt_fused(const float* __restrict__ ent,
                                                      const float* __restrict__ Wr,
                                                      const float* __restrict__ bias,
                                                      __nv_bfloat16* __restrict__ C,
                                                      int M) {
    extern __shared__ char sm[];
    uint32_t smb = smem_u32(sm);
    int tid  = threadIdx.x;
    int wid  = tid >> 5, lane = tid & 31;
    int wy   = wid >> 2, wx = wid & 3;
    int m0   = blockIdx.x * 128;
    int rows_valid = M - m0;

    if (tid < 128) ((float*)(sm + OFF_BIAS))[tid] = bias[tid];

    #pragma unroll
    for (int i = 0; i < 8; i++) {
        int g = tid + i * 256;
        int row = g >> 4, c8 = g & 15, col0 = c8 * 8;
        float4 v0 = make_float4(0.f, 0.f, 0.f, 0.f), v1 = v0;
        if (row < rows_valid) {
            const float4* p = (const float4*)(ent + (size_t)(m0 + row) * EDIM) + c8 * 2;
            v0 = p[0];
            v1 = p[1];
        }
        float ss = v0.x * v0.x + v0.y * v0.y + v0.z * v0.z + v0.w * v0.w +
                   v1.x * v1.x + v1.y * v1.y + v1.z * v1.z + v1.w * v1.w;
        #pragma unroll
        for (int o = 8; o; o >>= 1) ss += __shfl_xor_sync(0xffffffffu, ss, o);
        float n = sqrtf(ss);
        float s = fminf(1.0f, 1.0f / fmaxf(n, 1e-12f));
        float f[8] = {v0.x * s, v0.y * s, v0.z * s, v0.w * s,
                      v1.x * s, v1.y * s, v1.z * s, v1.w * s};
        if (row < rows_valid) {
            float4* q = (float4*)(g_EntN + (size_t)(m0 + row) * EDIM) + c8 * 2;
            q[0] = make_float4(f[0], f[1], f[2], f[3]);
            q[1] = make_float4(f[4], f[5], f[6], f[7]);
        }
        __nv_bfloat16 h[8];
        #pragma unroll
        for (int j = 0; j < 8; j++) h[j] = __float2bfloat16(f[j]);
        uint4 hv = make_uint4(pk_bf2(h[0], h[1]), pk_bf2(h[2], h[3]),
                              pk_bf2(h[4], h[5]), pk_bf2(h[6], h[7]));
        *(uint4*)(sm + OFF_AH + (size_t)row * LDT * 2 + col0 * 2) = hv;
    }

    load_hi(Wr, sm, OFF_BH1, tid);
    __syncthreads();

    int rowA  = wy * 64 + (lane & 15);
    int colA  = (lane >> 4) * 8;
    int nrow  = wx * 32 + (lane & 7) + ((lane >> 4) ? 8 : 0);
    int kaddB = ((lane >> 3) & 1) * 8;

    uint32_t aB = smb + OFF_AH, bB = smb + OFF_BH1;

    float d[4][4][4];
    #pragma unroll
    for (int i = 0; i < 4; i++)
        #pragma unroll
        for (int j = 0; j < 4; j++)
            #pragma unroll
            for (int q = 0; q < 4; q++) d[i][j][q] = 0.f;

    #pragma unroll
    for (int ks = 0; ks < 8; ks++) {
        int k0 = ks * 16;
        uint32_t a[4][4];
        #pragma unroll
        for (int mi = 0; mi < 4; mi++) {
            uint32_t addr = aB + (uint32_t)(((rowA + mi * 16) * LDT + k0 + colA) * 2);
            ldmx4(a[mi][0], a[mi][1], a[mi][2], a[mi][3], addr);
        }
        uint32_t b[4][2];
        #pragma unroll
        for (int nj2 = 0; nj2 < 2; nj2++) {
            uint32_t addr = bB + (uint32_t)(((nrow + nj2 * 16) * LDT + k0 + kaddB) * 2);
            uint32_t r0, r1, r2, r3;
            ldmx4(r0, r1, r2, r3, addr);
            b[nj2 * 2 + 0][0] = r0; b[nj2 * 2 + 0][1] = r1;
            b[nj2 * 2 + 1][0] = r2; b[nj2 * 2 + 1][1] = r3;
        }
        #pragma unroll
        for (int mi = 0; mi < 4; mi++)
            #pragma unroll
            for (int nj = 0; nj < 4; nj++)
                mma_bf16(d[mi][nj], a[mi], b[nj]);
    }

    const float* sb = (const float*)(sm + OFF_BIAS);
    int qrow = lane >> 2, qcol = (lane & 3) * 2;
    #pragma unroll
    for (int mi = 0; mi < 4; mi++) {
        #pragma unroll
        for (int half = 0; half < 2; half++) {
            int gm = m0 + wy * 64 + mi * 16 + qrow + half * 8;
            if (gm < M) {
                #pragma unroll
                for (int nj = 0; nj < 4; nj++) {
                    int gc = wx * 32 + nj * 8 + qcol;
                    float x0 = d[mi][nj][half * 2 + 0] + sb[gc];
                    float x1 = d[mi][nj][half * 2 + 1] + sb[gc + 1];
                    *(uint32_t*)(C + (size_t)gm * 128 + gc) =
                        pk_bf2(__float2bfloat16(x0), __float2bfloat16(x1));
                }
            }
        }
    }
}

// ---------------- rel-table max-norm (64 rows) ---------------------------------------
__global__ __launch_bounds__(256) void k_norm_rel(const float* __restrict__ rel) {
    int row = blockIdx.x * 8 + (threadIdx.x >> 5);
    int l   = threadIdx.x & 31;
    if (row >= N_RELS) return;
    float4 v = ((const float4*)(rel + (size_t)row * EDIM))[l];
    float ss = v.x * v.x + v.y * v.y + v.z * v.z + v.w * v.w;
    #pragma unroll
    for (int o = 16; o; o >>= 1) ss += __shfl_xor_sync(0xffffffffu, ss, o);
    float n = sqrtf(ss);
    float s = fminf(1.0f, 1.0f / fmaxf(n, 1e-12f));
    ((float4*)(g_RelN + (size_t)row * EDIM))[l] = make_float4(v.x * s, v.y * s, v.z * s, v.w * s);
}

// ---------------- k_main: attention; 8-lane-per-neighbor score reduction -------------
__global__ __launch_bounds__(128) void k_main(const int* __restrict__ idx,
                                              const int* __restrict__ adj_ent,
                                              const int* __restrict__ adj_rel) {
    __shared__ __align__(16) float s_hr[128];
    __shared__ __align__(16) float s_h[128];
    __shared__ float s_sc[32];
    __shared__ float s_att[32];
    __shared__ int   s_eid[32];
    __shared__ int   s_rid[32];

    int b   = blockIdx.x;
    int tid = threadIdx.x;

    int ib = idx[b];
    ib = min(max(ib, 0), N_ENTS - 1);

    if (tid < 32) {
        int e = adj_ent[(size_t)ib * KNBR + tid];
        s_eid[tid] = min(max(e, 0), N_ENTS - 1);
        int r = adj_rel[(size_t)ib * KNBR + tid];
        s_rid[tid] = min(max(r, 0), N_RELS - 1);
    }
    s_hr[tid] = __bfloat162float(g_TrTb[(size_t)ib * EDIM + tid]);
    s_h[tid]  = g_EntN[(size_t)ib * EDIM + tid];
    __syncthreads();

    int w = tid >> 5, l = tid & 31;
    int g = l >> 3, lg = l & 7;     // 4 groups of 8 lanes; lane covers 16 dims

    // hr slice for this lane: dims [lg*16, lg*16+16)
    float4 hr[4];
    #pragma unroll
    for (int j = 0; j < 4; j++) hr[j] = *(const float4*)(s_hr + lg * 16 + j * 4);

    // 4 neighbors in flight per warp; 2 iterations cover the warp's 8 neighbors
    #pragma unroll
    for (int it = 0; it < 2; it++) {
        int k = w * 8 + it * 4 + g;
        int e = s_eid[k], r = s_rid[k];
        const float4* rp = (const float4*)(g_RelN + (size_t)r * EDIM + lg * 16);
        const uint4*  tp = (const uint4*)(g_TrTb + (size_t)e * EDIM + lg * 16);
        uint4 t0 = tp[0], t1 = tp[1];
        uint32_t tw[8] = {t0.x, t0.y, t0.z, t0.w, t1.x, t1.y, t1.z, t1.w};
        float p = 0.f;
        #pragma unroll
        for (int j = 0; j < 4; j++) {
            float4 rv = rp[j];
            float2 ta = __bfloat1622float2(*(const __nv_bfloat162*)&tw[2 * j]);
            float2 tb = __bfloat1622float2(*(const __nv_bfloat162*)&tw[2 * j + 1]);
            p += tanh_hw(hr[j].x + rv.x) * ta.x + tanh_hw(hr[j].y + rv.y) * ta.y +
                 tanh_hw(hr[j].z + rv.z) * tb.x + tanh_hw(hr[j].w + rv.w) * tb.y;
        }
        p += __shfl_xor_sync(0xffffffffu, p, 1);
        p += __shfl_xor_sync(0xffffffffu, p, 2);
        p += __shfl_xor_sync(0xffffffffu, p, 4);
        if (lg == 0) s_sc[k] = p;
    }
    __syncthreads();

    if (tid < 32) {
        float sc = s_sc[tid];
        float mx = sc;
        #pragma unroll
        for (int o = 16; o; o >>= 1) mx = fmaxf(mx, __shfl_xor_sync(0xffffffffu, mx, o));
        float ex = __expf(sc - mx);
        float sum = ex;
        #pragma unroll
        for (int o = 16; o; o >>= 1) sum += __shfl_xor_sync(0xffffffffu, sum, o);
        s_att[tid] = ex / sum;
    }
    __syncthreads();

    float acc = 0.f;
    #pragma unroll
    for (int k = 0; k < KNBR; k++)
        acc = fmaf(s_att[k], g_EntN[(size_t)s_eid[k] * EDIM + tid], acc);

    float hv = s_h[tid];
    float x1 = hv + acc, x2 = hv * acc;
    size_t o = (size_t)b * EDIM + tid;
    __nv_bfloat16 h1 = __float2bfloat16(x1);
    g_X1h[o] = h1;
    g_X1l[o] = __float2bfloat16(x1 - __bfloat162float(h1));
    __nv_bfloat16 h2 = __float2bfloat16(x2);
    g_X2h[o] = h2;
    g_X2l[o] = __float2bfloat16(x2 - __bfloat162float(h2));
}

// ------- fused output with cp.async pipeline (round-11 proven) -----------------------
__device__ __forceinline__ void gemm_half(uint32_t smb, int aHoff, int aLoff,
                                          int bHoff, int bLoff,
                                          int rowA, int colA, int nrow, int kaddB,
                                          float d[2][4][4]) {
    #pragma unroll
    for (int ks = 0; ks < 8; ks++) {
        int k0 = ks * 16;
        #pragma unroll
        for (int pass = 0; pass < 3; pass++) {
            uint32_t aB = smb + ((pass == 2) ? aLoff : aHoff);
            uint32_t bB = smb + ((pass == 1) ? bLoff : bHoff);
            uint32_t a[2][4];
            #pragma unroll
            for (int mi = 0; mi < 2; mi++) {
                uint32_t addr = aB + (uint32_t)(((rowA + mi * 16) * LDT + k0 + colA) * 2);
                ldmx4(a[mi][0], a[mi][1], a[mi][2], a[mi][3], addr);
            }
            uint32_t b[4][2];
            #pragma unroll
            for (int nj2 = 0; nj2 < 2; nj2++) {
                uint32_t addr = bB + (uint32_t)(((nrow + nj2 * 16) * LDT + k0 + kaddB) * 2);
                uint32_t r0, r1, r2, r3;
                ldmx4(r0, r1, r2, r3, addr);
                b[nj2 * 2 + 0][0] = r0; b[nj2 * 2 + 0][1] = r1;
                b[nj2 * 2 + 1][0] = r2; b[nj2 * 2 + 1][1] = r3;
            }
            #pragma unroll
            for (int mi = 0; mi < 2; mi++)
                #pragma unroll
                for (int nj = 0; nj < 4; nj++)
                    mma_bf16(d[mi][nj], a[mi], b[nj]);
        }
    }
}

__global__ __launch_bounds__(256, 1) void k_out_fused(const float* __restrict__ W1,
                                                      const float* __restrict__ b1,
                                                      const float* __restrict__ W2,
                                                      const float* __restrict__ b2,
                                                      float* __restrict__ C, int M) {
    extern __shared__ char sm[];
    uint32_t smb = smem_u32(sm);
    int tid  = threadIdx.x;
    int wid  = tid >> 5, lane = tid & 31;
    int wy   = wid >> 1, wx = wid & 1;
    int m0   = blockIdx.x * 128;
    int n0   = blockIdx.y * 64;

    size_t aoff = (size_t)m0 * EDIM;
    copy128_async(g_X1h + aoff, smb, OA1H, tid);
    copy128_async(g_X1l + aoff, smb, OA1L, tid);
    CP_COMMIT();
    copy128_async(g_X2h + aoff, smb, OA2H, tid);
    copy128_async(g_X2l + aoff, smb, OA2L, tid);
    CP_COMMIT();

    if (tid < 64) {
        ((float*)(sm + OFF_B1))[tid] = b1[n0 + tid];
        ((float*)(sm + OFF_B2))[tid] = b2[n0 + tid];
    }
    load_split64(W1 + (size_t)n0 * EDIM, sm, OW1H, OW1L, tid);
    load_split64(W2 + (size_t)n0 * EDIM, sm, OW2H, OW2L, tid);

    int rowA  = wy * 32 + (lane & 15);
    int colA  = (lane >> 4) * 8;
    int nrow  = wx * 32 + (lane & 7) + ((lane >> 4) ? 8 : 0);
    int kaddB = ((lane >> 3) & 1) * 8;

    float d1[2][4][4], d2[2][4][4];
    #pragma unroll
    for (int i = 0; i < 2; i++)
        #pragma unroll
        for (int j = 0; j < 4; j++)
            #pragma unroll
            for (int q = 0; q < 4; q++) { d1[i][j][q] = 0.f; d2[i][j][q] = 0.f; }

    CP_WAIT(1);
    __syncthreads();
    gemm_half(smb, OA1H, OA1L, OW1H, OW1L, rowA, colA, nrow, kaddB, d1);

    CP_WAIT(0);
    __syncthreads();
    gemm_half(smb, OA2H, OA2L, OW2H, OW2L, rowA, colA, nrow, kaddB, d2);

    const float* sb1 = (const float*)(sm + OFF_B1);
    const float* sb2 = (const float*)(sm + OFF_B2);
    int qrow = lane >> 2, qcol = (lane & 3) * 2;
    #pragma unroll
    for (int mi = 0; mi < 2; mi++) {
        #pragma unroll
        for (int half = 0; half < 2; half++) {
            int gm = m0 + wy * 32 + mi * 16 + qrow + half * 8;
            #pragma unroll
            for (int nj = 0; nj < 4; nj++) {
                int gc = wx * 32 + nj * 8 + qcol;
                float u0 = d1[mi][nj][half * 2 + 0] + sb1[gc];
                float u1 = d1[mi][nj][half * 2 + 1] + sb1[gc + 1];
                float v0 = d2[mi][nj][half * 2 + 0] + sb2[gc];
                float v1 = d2[mi][nj][half * 2 + 1] + sb2[gc + 1];
                u0 = (u0 > 0.f) ? u0 : 0.2f * u0;
                u1 = (u1 > 0.f) ? u1 : 0.2f * u1;
                v0 = (v0 > 0.f) ? v0 : 0.2f * v0;
                v1 = (v1 > 0.f) ? v1 : 0.2f * v1;
                *(float2*)(C + (size_t)gm * 128 + n0 + gc) = make_float2(u0 + v0, u1 + v1);
            }
        }
    }
}

// ---------------- launch ---------------------------------------------------------------
extern "C" void kernel_launch(void* const* d_in, const int* in_sizes, int n_in,
                              void* d_out, int out_size) {
    const int*   idx     = (const int*)d_in[0];
    const int*   adj_ent = (const int*)d_in[1];
    const int*   adj_rel = (const int*)d_in[2];
    const float* ent     = (const float*)d_in[3];
    const float* rel     = (const float*)d_in[4];
    const float* Wr_w    = (const float*)d_in[5];
    const float* Wr_b    = (const float*)d_in[6];
    const float* W1_w    = (const float*)d_in[7];
    const float* W1_b    = (const float*)d_in[8];
    const float* W2_w    = (const float*)d_in[9];
    const float* W2_b    = (const float*)d_in[10];
    float* out = (float*)d_out;

    cudaFuncSetAttribute(k_trt_fused, cudaFuncAttributeMaxDynamicSharedMemorySize, SMEM_TRT);
    cudaFuncSetAttribute(k_out_fused, cudaFuncAttributeMaxDynamicSharedMemorySize, SMEM_OUT);

    __nv_bfloat16* TrTb;
    cudaGetSymbolAddress((void**)&TrTb, g_TrTb);

    k_norm_rel<<<(N_RELS + 7) / 8, 256>>>(rel);
    k_trt_fused<<<(N_ENTS + 127) / 128, 256, SMEM_TRT>>>(ent, Wr_w, Wr_b, TrTb, N_ENTS);
    k_main<<<BATCH, 128>>>(idx, adj_ent, adj_rel);
    dim3 go(BATCH / 128, 2);
    k_out_fused<<<go, 256, SMEM_OUT>>>(W1_w, W1_b, W2_w, W2_b, out, BATCH);
}

// round 13
// speedup vs baseline: 1.1388x; 1.1388x over previous
#include <cuda_runtime.h>
#include <cuda_bf16.h>
#include <math.h>
#include <stdint.h>

#define N_ENTS  100000
#define N_RELS  64
#define EDIM    128
#define KNBR    32
#define BATCH   16384

// ---------------- device-global scratch ------------------------------------------
__device__ float         g_EntN[(size_t)N_ENTS * EDIM];   // maxnorm(ent) fp32
__device__ __nv_bfloat16 g_TrTb[(size_t)N_ENTS * EDIM];   // bf16(EntN @ Wr^T + b)
__device__ float         g_RelN[(size_t)N_RELS * EDIM];
__device__ __nv_bfloat16 g_X1h[(size_t)BATCH * EDIM];
__device__ __nv_bfloat16 g_X1l[(size_t)BATCH * EDIM];
__device__ __nv_bfloat16 g_X2h[(size_t)BATCH * EDIM];
__device__ __nv_bfloat16 g_X2l[(size_t)BATCH * EDIM];

// ---------------- helpers ----------------------------------------------------------
__device__ __forceinline__ uint32_t smem_u32(const void* p) {
    uint32_t a;
    asm("{ .reg .u64 t; cvta.to.shared.u64 t, %1; cvt.u32.u64 %0, t; }" : "=r"(a) : "l"(p));
    return a;
}
__device__ __forceinline__ void ldmx4(uint32_t& r0, uint32_t& r1, uint32_t& r2, uint32_t& r3,
                                      uint32_t addr) {
    asm volatile("ldmatrix.sync.aligned.m8n8.x4.shared.b16 {%0,%1,%2,%3}, [%4];"
                 : "=r"(r0), "=r"(r1), "=r"(r2), "=r"(r3) : "r"(addr));
}
__device__ __forceinline__ void mma_bf16(float* d, const uint32_t* a, const uint32_t* b) {
    asm volatile(
        "mma.sync.aligned.m16n8k16.row.col.f32.bf16.bf16.f32 "
        "{%0,%1,%2,%3}, {%4,%5,%6,%7}, {%8,%9}, {%0,%1,%2,%3};"
        : "+f"(d[0]), "+f"(d[1]), "+f"(d[2]), "+f"(d[3])
        : "r"(a[0]), "r"(a[1]), "r"(a[2]), "r"(a[3]), "r"(b[0]), "r"(b[1]));
}
__device__ __forceinline__ uint32_t pk_bf2(__nv_bfloat16 a, __nv_bfloat16 b) {
    __nv_bfloat162 t(a, b);
    return *(uint32_t*)&t;
}
__device__ __forceinline__ float tanh_hw(float x) {
    float y;
    asm("tanh.approx.f32 %0, %1;" : "=f"(y) : "f"(x));
    return y;
}
__device__ __forceinline__ void cp16(uint32_t dst, const void* src) {
    asm volatile("cp.async.cg.shared.global [%0], [%1], 16;" :: "r"(dst), "l"(src));
}
#define CP_COMMIT() asm volatile("cp.async.commit_group;" ::: "memory")
#define CP_WAIT(n)  asm volatile("cp.async.wait_group %0;" :: "n"(n) : "memory")

// padded bf16 tiles, row stride 136 elems (272 B) -> conflict-free ldmatrix
#define LDT 136
#define TILE_B  (128 * LDT * 2)   // 34816
#define HTILE_B (64  * LDT * 2)   // 17408
// TrT kernel layout
#define OFF_BIAS 0
#define OFF_AH   512
#define OFF_BH1  (512 + TILE_B)
#define SMEM_TRT (512 + 2 * TILE_B)              // 70,144 -> 2 CTAs/SM
// fused output kernel layout
#define OFF_B1   0
#define OFF_B2   256
#define OA1H     512
#define OA1L     (512 + TILE_B)
#define OA2H     (512 + 2 * TILE_B)
#define OA2L     (512 + 3 * TILE_B)
#define OW1H     (512 + 4 * TILE_B)
#define OW1L     (512 + 4 * TILE_B + HTILE_B)
#define OW2H     (512 + 4 * TILE_B + 2 * HTILE_B)
#define OW2L     (512 + 4 * TILE_B + 3 * HTILE_B)
#define SMEM_OUT (512 + 4 * TILE_B + 4 * HTILE_B)   // 209,408 -> 1 CTA/SM

// async bf16 tile copy: gmem (stride 128) -> padded smem, 128 rows
__device__ __forceinline__ void copy128_async(const __nv_bfloat16* __restrict__ src,
                                              uint32_t smb, int off, int tid) {
    #pragma unroll
    for (int i = 0; i < 8; i++) {
        int g = tid + i * 256;
        int row = g >> 4, c8 = g & 15;
        cp16(smb + off + row * LDT * 2 + c8 * 16, src + (size_t)row * EDIM + c8 * 8);
    }
}
// fp32 -> bf16 hi/lo split, 64 rows
__device__ __forceinline__ void load_split64(const float* __restrict__ src,
                                             char* sm, int off_h, int off_l, int tid) {
    #pragma unroll
    for (int i = 0; i < 4; i++) {
        int g = tid + i * 256;
        int row = g >> 4, c8 = g & 15, col0 = c8 * 8;
        const float4* p = (const float4*)src + (size_t)row * 32 + c8 * 2;
        float4 v0 = p[0], v1 = p[1];
        float f[8] = {v0.x, v0.y, v0.z, v0.w, v1.x, v1.y, v1.z, v1.w};
        __nv_bfloat16 h[8], l[8];
        #pragma unroll
        for (int j = 0; j < 8; j++) {
            h[j] = __float2bfloat16(f[j]);
            l[j] = __float2bfloat16(f[j] - __bfloat162float(h[j]));
        }
        uint4 hv = make_uint4(pk_bf2(h[0], h[1]), pk_bf2(h[2], h[3]),
                              pk_bf2(h[4], h[5]), pk_bf2(h[6], h[7]));
        uint4 lv = make_uint4(pk_bf2(l[0], l[1]), pk_bf2(l[2], l[3]),
                              pk_bf2(l[4], l[5]), pk_bf2(l[6], l[7]));
        size_t o = (size_t)row * LDT * 2 + col0 * 2;
        *(uint4*)(sm + off_h + o) = hv;
        *(uint4*)(sm + off_l + o) = lv;
    }
}
// hi-only fp32->bf16, 128 rows
__device__ __forceinline__ void load_hi(const float* __restrict__ src,
                                        char* sm, int off_h, int tid) {
    #pragma unroll
    for (int i = 0; i < 8; i++) {
        int g = tid + i * 256;
        int row = g >> 4, c8 = g & 15, col0 = c8 * 8;
        const float4* p = (const float4*)src + (size_t)row * 32 + c8 * 2;
        float4 v0 = p[0], v1 = p[1];
        float f[8] = {v0.x, v0.y, v0.z, v0.w, v1.x, v1.y, v1.z, v1.w};
        __nv_bfloat16 h[8];
        #pragma unroll
        for (int j = 0; j < 8; j++) h[j] = __float2bfloat16(f[j]);
        uint4 hv = make_uint4(pk_bf2(h[0], h[1]), pk_bf2(h[2], h[3]),
                              pk_bf2(h[4], h[5]), pk_bf2(h[6], h[7]));
        *(uint4*)(sm + off_h + (size_t)row * LDT * 2 + col0 * 2) = hv;
    }
}

// ---------- fused: rel-norm (block 0) + ent maxnorm + 1-pass bf16 GEMM + EntN --------
__global__ __launch_bounds__(256, 2) void k_trt_fused(const float* __restrict__ ent,
                                                      const float* __restrict__ rel,
                                                      const float* __restrict__ Wr,
                                                      const float* __restrict__ bias,
                                                      __nv_bfloat16* __restrict__ C,
                                                      int M) {
    extern __shared__ char sm[];
    uint32_t smb = smem_u32(sm);
    int tid  = threadIdx.x;
    int wid  = tid >> 5, lane = tid & 31;
    int wy   = wid >> 2, wx = wid & 3;
    int m0   = blockIdx.x * 128;
    int rows_valid = M - m0;

    // block 0 additionally normalizes the 64-row rel table (warp-per-row)
    if (blockIdx.x == 0) {
        #pragma unroll
        for (int r8 = 0; r8 < 8; r8++) {
            int row = wid * 8 + r8;
            float4 v = ((const float4*)(rel + (size_t)row * EDIM))[lane];
            float ss = v.x * v.x + v.y * v.y + v.z * v.z + v.w * v.w;
            #pragma unroll
            for (int o = 16; o; o >>= 1) ss += __shfl_xor_sync(0xffffffffu, ss, o);
            float n = sqrtf(ss);
            float s = fminf(1.0f, 1.0f / fmaxf(n, 1e-12f));
            ((float4*)(g_RelN + (size_t)row * EDIM))[lane] =
                make_float4(v.x * s, v.y * s, v.z * s, v.w * s);
        }
    }

    if (tid < 128) ((float*)(sm + OFF_BIAS))[tid] = bias[tid];

    #pragma unroll
    for (int i = 0; i < 8; i++) {
        int g = tid + i * 256;
        int row = g >> 4, c8 = g & 15, col0 = c8 * 8;
        float4 v0 = make_float4(0.f, 0.f, 0.f, 0.f), v1 = v0;
        if (row < rows_valid) {
            const float4* p = (const float4*)(ent + (size_t)(m0 + row) * EDIM) + c8 * 2;
            v0 = p[0];
            v1 = p[1];
        }
        float ss = v0.x * v0.x + v0.y * v0.y + v0.z * v0.z + v0.w * v0.w +
                   v1.x * v1.x + v1.y * v1.y + v1.z * v1.z + v1.w * v1.w;
        #pragma unroll
        for (int o = 8; o; o >>= 1) ss += __shfl_xor_sync(0xffffffffu, ss, o);
        float n = sqrtf(ss);
        float s = fminf(1.0f, 1.0f / fmaxf(n, 1e-12f));
        float f[8] = {v0.x * s, v0.y * s, v0.z * s, v0.w * s,
                      v1.x * s, v1.y * s, v1.z * s, v1.w * s};
        if (row < rows_valid) {
            float4* q = (float4*)(g_EntN + (size_t)(m0 + row) * EDIM) + c8 * 2;
            q[0] = make_float4(f[0], f[1], f[2], f[3]);
            q[1] = make_float4(f[4], f[5], f[6], f[7]);
        }
        __nv_bfloat16 h[8];
        #pragma unroll
        for (int j = 0; j < 8; j++) h[j] = __float2bfloat16(f[j]);
        uint4 hv = make_uint4(pk_bf2(h[0], h[1]), pk_bf2(h[2], h[3]),
                              pk_bf2(h[4], h[5]), pk_bf2(h[6], h[7]));
        *(uint4*)(sm + OFF_AH + (size_t)row * LDT * 2 + col0 * 2) = hv;
    }

    load_hi(Wr, sm, OFF_BH1, tid);
    __syncthreads();

    int rowA  = wy * 64 + (lane & 15);
    int colA  = (lane >> 4) * 8;
    int nrow  = wx * 32 + (lane & 7) + ((lane >> 4) ? 8 : 0);
    int kaddB = ((lane >> 3) & 1) * 8;

    uint32_t aB = smb + OFF_AH, bB = smb + OFF_BH1;

    float d[4][4][4];
    #pragma unroll
    for (int i = 0; i < 4; i++)
        #pragma unroll
        for (int j = 0; j < 4; j++)
            #pragma unroll
            for (int q = 0; q < 4; q++) d[i][j][q] = 0.f;

    #pragma unroll
    for (int ks = 0; ks < 8; ks++) {
        int k0 = ks * 16;
        uint32_t a[4][4];
        #pragma unroll
        for (int mi = 0; mi < 4; mi++) {
            uint32_t addr = aB + (uint32_t)(((rowA + mi * 16) * LDT + k0 + colA) * 2);
            ldmx4(a[mi][0], a[mi][1], a[mi][2], a[mi][3], addr);
        }
        uint32_t b[4][2];
        #pragma unroll
        for (int nj2 = 0; nj2 < 2; nj2++) {
            uint32_t addr = bB + (uint32_t)(((nrow + nj2 * 16) * LDT + k0 + kaddB) * 2);
            uint32_t r0, r1, r2, r3;
            ldmx4(r0, r1, r2, r3, addr);
            b[nj2 * 2 + 0][0] = r0; b[nj2 * 2 + 0][1] = r1;
            b[nj2 * 2 + 1][0] = r2; b[nj2 * 2 + 1][1] = r3;
        }
        #pragma unroll
        for (int mi = 0; mi < 4; mi++)
            #pragma unroll
            for (int nj = 0; nj < 4; nj++)
                mma_bf16(d[mi][nj], a[mi], b[nj]);
    }

    const float* sb = (const float*)(sm + OFF_BIAS);
    int qrow = lane >> 2, qcol = (lane & 3) * 2;
    #pragma unroll
    for (int mi = 0; mi < 4; mi++) {
        #pragma unroll
        for (int half = 0; half < 2; half++) {
            int gm = m0 + wy * 64 + mi * 16 + qrow + half * 8;
            if (gm < M) {
                #pragma unroll
                for (int nj = 0; nj < 4; nj++) {
                    int gc = wx * 32 + nj * 8 + qcol;
                    float x0 = d[mi][nj][half * 2 + 0] + sb[gc];
                    float x1 = d[mi][nj][half * 2 + 1] + sb[gc + 1];
                    *(uint32_t*)(C + (size_t)gm * 128 + gc) =
                        pk_bf2(__float2bfloat16(x0), __float2bfloat16(x1));
                }
            }
        }
    }
}

// ---------------- k_main: attention + aggregation (round-9/11 proven) ----------------
__global__ __launch_bounds__(128) void k_main(const int* __restrict__ idx,
                                              const int* __restrict__ adj_ent,
                                              const int* __restrict__ adj_rel) {
    __shared__ __align__(16) float s_hr[128];
    __shared__ __align__(16) float s_h[128];
    __shared__ float s_sc[32];
    __shared__ float s_att[32];
    __shared__ int   s_eid[32];
    __shared__ int   s_rid[32];

    int b   = blockIdx.x;
    int tid = threadIdx.x;

    int ib = idx[b];
    ib = min(max(ib, 0), N_ENTS - 1);

    if (tid < 32) {
        int e = adj_ent[(size_t)ib * KNBR + tid];
        s_eid[tid] = min(max(e, 0), N_ENTS - 1);
        int r = adj_rel[(size_t)ib * KNBR + tid];
        s_rid[tid] = min(max(r, 0), N_RELS - 1);
    }
    s_hr[tid] = __bfloat162float(g_TrTb[(size_t)ib * EDIM + tid]);
    s_h[tid]  = g_EntN[(size_t)ib * EDIM + tid];
    __syncthreads();

    int w = tid >> 5, l = tid & 31;
    float4 hr4 = *(const float4*)(s_hr + l * 4);

    #pragma unroll
    for (int kk = 0; kk < 8; kk++) {
        int k = w * 8 + kk;
        int e = s_eid[k], r = s_rid[k];
        uint2 trb = *(const uint2*)(g_TrTb + (size_t)e * EDIM + l * 4);
        float2 t01 = __bfloat1622float2(*(const __nv_bfloat162*)&trb.x);
        float2 t23 = __bfloat1622float2(*(const __nv_bfloat162*)&trb.y);
        float4 rv = *(const float4*)(g_RelN + (size_t)r * EDIM + l * 4);
        float p = tanh_hw(hr4.x + rv.x) * t01.x + tanh_hw(hr4.y + rv.y) * t01.y +
                  tanh_hw(hr4.z + rv.z) * t23.x + tanh_hw(hr4.w + rv.w) * t23.y;
        #pragma unroll
        for (int o = 16; o; o >>= 1) p += __shfl_xor_sync(0xffffffffu, p, o);
        if (l == 0) s_sc[k] = p;
    }
    __syncthreads();

    if (tid < 32) {
        float sc = s_sc[tid];
        float mx = sc;
        #pragma unroll
        for (int o = 16; o; o >>= 1) mx = fmaxf(mx, __shfl_xor_sync(0xffffffffu, mx, o));
        float ex = __expf(sc - mx);
        float sum = ex;
        #pragma unroll
        for (int o = 16; o; o >>= 1) sum += __shfl_xor_sync(0xffffffffu, sum, o);
        s_att[tid] = ex / sum;
    }
    __syncthreads();

    float acc = 0.f;
    #pragma unroll
    for (int k = 0; k < KNBR; k++)
        acc = fmaf(s_att[k], g_EntN[(size_t)s_eid[k] * EDIM + tid], acc);

    float hv = s_h[tid];
    float x1 = hv + acc, x2 = hv * acc;
    size_t o = (size_t)b * EDIM + tid;
    __nv_bfloat16 h1 = __float2bfloat16(x1);
    g_X1h[o] = h1;
    g_X1l[o] = __float2bfloat16(x1 - __bfloat162float(h1));
    __nv_bfloat16 h2 = __float2bfloat16(x2);
    g_X2h[o] = h2;
    g_X2l[o] = __float2bfloat16(x2 - __bfloat162float(h2));
}

// ------- fused output with cp.async pipeline (round-11 proven) -----------------------
__device__ __forceinline__ void gemm_half(uint32_t smb, int aHoff, int aLoff,
                                          int bHoff, int bLoff,
                                          int rowA, int colA, int nrow, int kaddB,
                                          float d[2][4][4]) {
    #pragma unroll
    for (int ks = 0; ks < 8; ks++) {
        int k0 = ks * 16;
        #pragma unroll
        for (int pass = 0; pass < 3; pass++) {
            uint32_t aB = smb + ((pass == 2) ? aLoff : aHoff);
            uint32_t bB = smb + ((pass == 1) ? bLoff : bHoff);
            uint32_t a[2][4];
            #pragma unroll
            for (int mi = 0; mi < 2; mi++) {
                uint32_t addr = aB + (uint32_t)(((rowA + mi * 16) * LDT + k0 + colA) * 2);
                ldmx4(a[mi][0], a[mi][1], a[mi][2], a[mi][3], addr);
            }
            uint32_t b[4][2];
            #pragma unroll
            for (int nj2 = 0; nj2 < 2; nj2++) {
                uint32_t addr = bB + (uint32_t)(((nrow + nj2 * 16) * LDT + k0 + kaddB) * 2);
                uint32_t r0, r1, r2, r3;
                ldmx4(r0, r1, r2, r3, addr);
                b[nj2 * 2 + 0][0] = r0; b[nj2 * 2 + 0][1] = r1;
                b[nj2 * 2 + 1][0] = r2; b[nj2 * 2 + 1][1] = r3;
            }
            #pragma unroll
            for (int mi = 0; mi < 2; mi++)
                #pragma unroll
                for (int nj = 0; nj < 4; nj++)
                    mma_bf16(d[mi][nj], a[mi], b[nj]);
        }
    }
}

__global__ __launch_bounds__(256, 1) void k_out_fused(const float* __restrict__ W1,
                                                      const float* __restrict__ b1,
                                                      const float* __restrict__ W2,
                                                      const float* __restrict__ b2,
                                                      float* __restrict__ C, int M) {
    extern __shared__ char sm[];
    uint32_t smb = smem_u32(sm);
    int tid  = threadIdx.x;
    int wid  = tid >> 5, lane = tid & 31;
    int wy   = wid >> 1, wx = wid & 1;
    int m0   = blockIdx.x * 128;
    int n0   = blockIdx.y * 64;

    size_t aoff = (size_t)m0 * EDIM;
    copy128_async(g_X1h + aoff, smb, OA1H, tid);
    copy128_async(g_X1l + aoff, smb, OA1L, tid);
    CP_COMMIT();
    copy128_async(g_X2h + aoff, smb, OA2H, tid);
    copy128_async(g_X2l + aoff, smb, OA2L, tid);
    CP_COMMIT();

    if (tid < 64) {
        ((float*)(sm + OFF_B1))[tid] = b1[n0 + tid];
        ((float*)(sm + OFF_B2))[tid] = b2[n0 + tid];
    }
    load_split64(W1 + (size_t)n0 * EDIM, sm, OW1H, OW1L, tid);
    load_split64(W2 + (size_t)n0 * EDIM, sm, OW2H, OW2L, tid);

    int rowA  = wy * 32 + (lane & 15);
    int colA  = (lane >> 4) * 8;
    int nrow  = wx * 32 + (lane & 7) + ((lane >> 4) ? 8 : 0);
    int kaddB = ((lane >> 3) & 1) * 8;

    float d1[2][4][4], d2[2][4][4];
    #pragma unroll
    for (int i = 0; i < 2; i++)
        #pragma unroll
        for (int j = 0; j < 4; j++)
            #pragma unroll
            for (int q = 0; q < 4; q++) { d1[i][j][q] = 0.f; d2[i][j][q] = 0.f; }

    CP_WAIT(1);
    __syncthreads();
    gemm_half(smb, OA1H, OA1L, OW1H, OW1L, rowA, colA, nrow, kaddB, d1);

    CP_WAIT(0);
    __syncthreads();
    gemm_half(smb, OA2H, OA2L, OW2H, OW2L, rowA, colA, nrow, kaddB, d2);

    const float* sb1 = (const float*)(sm + OFF_B1);
    const float* sb2 = (const float*)(sm + OFF_B2);
    int qrow = lane >> 2, qcol = (lane & 3) * 2;
    #pragma unroll
    for (int mi = 0; mi < 2; mi++) {
        #pragma unroll
        for (int half = 0; half < 2; half++) {
            int gm = m0 + wy * 32 + mi * 16 + qrow + half * 8;
            #pragma unroll
            for (int nj = 0; nj < 4; nj++) {
                int gc = wx * 32 + nj * 8 + qcol;
                float u0 = d1[mi][nj][half * 2 + 0] + sb1[gc];
                float u1 = d1[mi][nj][half * 2 + 1] + sb1[gc + 1];
                float v0 = d2[mi][nj][half * 2 + 0] + sb2[gc];
                float v1 = d2[mi][nj][half * 2 + 1] + sb2[gc + 1];
                u0 = (u0 > 0.f) ? u0 : 0.2f * u0;
                u1 = (u1 > 0.f) ? u1 : 0.2f * u1;
                v0 = (v0 > 0.f) ? v0 : 0.2f * v0;
                v1 = (v1 > 0.f) ? v1 : 0.2f * v1;
                *(float2*)(C + (size_t)gm * 128 + n0 + gc) = make_float2(u0 + v0, u1 + v1);
            }
        }
    }
}

// ---------------- launch ---------------------------------------------------------------
extern "C" void kernel_launch(void* const* d_in, const int* in_sizes, int n_in,
                              void* d_out, int out_size) {
    const int*   idx     = (const int*)d_in[0];
    const int*   adj_ent = (const int*)d_in[1];
    const int*   adj_rel = (const int*)d_in[2];
    const float* ent     = (const float*)d_in[3];
    const float* rel     = (const float*)d_in[4];
    const float* Wr_w    = (const float*)d_in[5];
    const float* Wr_b    = (const float*)d_in[6];
    const float* W1_w    = (const float*)d_in[7];
    const float* W1_b    = (const float*)d_in[8];
    const float* W2_w    = (const float*)d_in[9];
    const float* W2_b    = (const float*)d_in[10];
    float* out = (float*)d_out;

    cudaFuncSetAttribute(k_trt_fused, cudaFuncAttributeMaxDynamicSharedMemorySize, SMEM_TRT);
    cudaFuncSetAttribute(k_out_fused, cudaFuncAttributeMaxDynamicSharedMemorySize, SMEM_OUT);

    __nv_bfloat16* TrTb;
    cudaGetSymbolAddress((void**)&TrTb, g_TrTb);

    k_trt_fused<<<(N_ENTS + 127) / 128, 256, SMEM_TRT>>>(ent, rel, Wr_w, Wr_b, TrTb, N_ENTS);
    k_main<<<BATCH, 128>>>(idx, adj_ent, adj_rel);
    dim3 go(BATCH / 128, 2);
    k_out_fused<<<go, 256, SMEM_OUT>>>(W1_w, W1_b, W2_w, W2_b, out, BATCH);
}

// round 14
// speedup vs baseline: 1.1873x; 1.0426x over previous
#include <cuda_runtime.h>
#include <cuda_bf16.h>
#include <math.h>
#include <stdint.h>

#define N_ENTS  100000
#define N_RELS  64
#define EDIM    128
#define KNBR    32
#define BATCH   16384

// ---------------- device-global scratch ------------------------------------------
__device__ float         g_Scale[N_ENTS];                 // per-row maxnorm scale
__device__ __nv_bfloat16 g_TrTb[(size_t)N_ENTS * EDIM];   // bf16(maxnorm(ent) @ Wr^T + b)
__device__ float         g_RelN[(size_t)N_RELS * EDIM];
__device__ __nv_bfloat16 g_X1h[(size_t)BATCH * EDIM];
__device__ __nv_bfloat16 g_X1l[(size_t)BATCH * EDIM];
__device__ __nv_bfloat16 g_X2h[(size_t)BATCH * EDIM];
__device__ __nv_bfloat16 g_X2l[(size_t)BATCH * EDIM];

// ---------------- helpers ----------------------------------------------------------
__device__ __forceinline__ uint32_t smem_u32(const void* p) {
    uint32_t a;
    asm("{ .reg .u64 t; cvta.to.shared.u64 t, %1; cvt.u32.u64 %0, t; }" : "=r"(a) : "l"(p));
    return a;
}
__device__ __forceinline__ void ldmx4(uint32_t& r0, uint32_t& r1, uint32_t& r2, uint32_t& r3,
                                      uint32_t addr) {
    asm volatile("ldmatrix.sync.aligned.m8n8.x4.shared.b16 {%0,%1,%2,%3}, [%4];"
                 : "=r"(r0), "=r"(r1), "=r"(r2), "=r"(r3) : "r"(addr));
}
__device__ __forceinline__ void mma_bf16(float* d, const uint32_t* a, const uint32_t* b) {
    asm volatile(
        "mma.sync.aligned.m16n8k16.row.col.f32.bf16.bf16.f32 "
        "{%0,%1,%2,%3}, {%4,%5,%6,%7}, {%8,%9}, {%0,%1,%2,%3};"
        : "+f"(d[0]), "+f"(d[1]), "+f"(d[2]), "+f"(d[3])
        : "r"(a[0]), "r"(a[1]), "r"(a[2]), "r"(a[3]), "r"(b[0]), "r"(b[1]));
}
__device__ __forceinline__ uint32_t pk_bf2(__nv_bfloat16 a, __nv_bfloat16 b) {
    __nv_bfloat162 t(a, b);
    return *(uint32_t*)&t;
}
__device__ __forceinline__ float tanh_hw(float x) {
    float y;
    asm("tanh.approx.f32 %0, %1;" : "=f"(y) : "f"(x));
    return y;
}
__device__ __forceinline__ void cp16(uint32_t dst, const void* src) {
    asm volatile("cp.async.cg.shared.global [%0], [%1], 16;" :: "r"(dst), "l"(src));
}
#define CP_COMMIT() asm volatile("cp.async.commit_group;" ::: "memory")
#define CP_WAIT(n)  asm volatile("cp.async.wait_group %0;" :: "n"(n) : "memory")

// padded bf16 tiles, row stride 136 elems (272 B) -> conflict-free ldmatrix
#define LDT 136
#define TILE_B  (128 * LDT * 2)   // 34816
#define HTILE_B (64  * LDT * 2)   // 17408
// TrT kernel layout
#define OFF_BIAS 0
#define OFF_AH   512
#define OFF_BH1  (512 + TILE_B)
#define SMEM_TRT (512 + 2 * TILE_B)              // 70,144 -> 2 CTAs/SM
// fused output kernel layout
#define OFF_B1   0
#define OFF_B2   256
#define OA1H     512
#define OA1L     (512 + TILE_B)
#define OA2H     (512 + 2 * TILE_B)
#define OA2L     (512 + 3 * TILE_B)
#define OW1H     (512 + 4 * TILE_B)
#define OW1L     (512 + 4 * TILE_B + HTILE_B)
#define OW2H     (512 + 4 * TILE_B + 2 * HTILE_B)
#define OW2L     (512 + 4 * TILE_B + 3 * HTILE_B)
#define SMEM_OUT (512 + 4 * TILE_B + 4 * HTILE_B)   // 209,408 -> 1 CTA/SM

// async bf16 tile copy: gmem (stride 128) -> padded smem, 128 rows
__device__ __forceinline__ void copy128_async(const __nv_bfloat16* __restrict__ src,
                                              uint32_t smb, int off, int tid) {
    #pragma unroll
    for (int i = 0; i < 8; i++) {
        int g = tid + i * 256;
        int row = g >> 4, c8 = g & 15;
        cp16(smb + off + row * LDT * 2 + c8 * 16, src + (size_t)row * EDIM + c8 * 8);
    }
}
// fp32 -> bf16 hi/lo split, 64 rows
__device__ __forceinline__ void load_split64(const float* __restrict__ src,
                                             char* sm, int off_h, int off_l, int tid) {
    #pragma unroll
    for (int i = 0; i < 4; i++) {
        int g = tid + i * 256;
        int row = g >> 4, c8 = g & 15, col0 = c8 * 8;
        const float4* p = (const float4*)src + (size_t)row * 32 + c8 * 2;
        float4 v0 = p[0], v1 = p[1];
        float f[8] = {v0.x, v0.y, v0.z, v0.w, v1.x, v1.y, v1.z, v1.w};
        __nv_bfloat16 h[8], l[8];
        #pragma unroll
        for (int j = 0; j < 8; j++) {
            h[j] = __float2bfloat16(f[j]);
            l[j] = __float2bfloat16(f[j] - __bfloat162float(h[j]));
        }
        uint4 hv = make_uint4(pk_bf2(h[0], h[1]), pk_bf2(h[2], h[3]),
                              pk_bf2(h[4], h[5]), pk_bf2(h[6], h[7]));
        uint4 lv = make_uint4(pk_bf2(l[0], l[1]), pk_bf2(l[2], l[3]),
                              pk_bf2(l[4], l[5]), pk_bf2(l[6], l[7]));
        size_t o = (size_t)row * LDT * 2 + col0 * 2;
        *(uint4*)(sm + off_h + o) = hv;
        *(uint4*)(sm + off_l + o) = lv;
    }
}
// hi-only fp32->bf16, 128 rows
__device__ __forceinline__ void load_hi(const float* __restrict__ src,
                                        char* sm, int off_h, int tid) {
    #pragma unroll
    for (int i = 0; i < 8; i++) {
        int g = tid + i * 256;
        int row = g >> 4, c8 = g & 15, col0 = c8 * 8;
        const float4* p = (const float4*)src + (size_t)row * 32 + c8 * 2;
        float4 v0 = p[0], v1 = p[1];
        float f[8] = {v0.x, v0.y, v0.z, v0.w, v1.x, v1.y, v1.z, v1.w};
        __nv_bfloat16 h[8];
        #pragma unroll
        for (int j = 0; j < 8; j++) h[j] = __float2bfloat16(f[j]);
        uint4 hv = make_uint4(pk_bf2(h[0], h[1]), pk_bf2(h[2], h[3]),
                              pk_bf2(h[4], h[5]), pk_bf2(h[6], h[7]));
        *(uint4*)(sm + off_h + (size_t)row * LDT * 2 + col0 * 2) = hv;
    }
}

// ---------- fused: rel-norm (block 0) + ent maxnorm -> scale + 1-pass GEMM -> TrTb ---
__global__ __launch_bounds__(256, 2) void k_trt_fused(const float* __restrict__ ent,
                                                      const float* __restrict__ rel,
                                                      const float* __restrict__ Wr,
                                                      const float* __restrict__ bias,
                                                      __nv_bfloat16* __restrict__ C,
                                                      int M) {
    extern __shared__ char sm[];
    uint32_t smb = smem_u32(sm);
    int tid  = threadIdx.x;
    int wid  = tid >> 5, lane = tid & 31;
    int wy   = wid >> 2, wx = wid & 3;
    int m0   = blockIdx.x * 128;
    int rows_valid = M - m0;

    // block 0 additionally normalizes the 64-row rel table (warp-per-row)
    if (blockIdx.x == 0) {
        #pragma unroll
        for (int r8 = 0; r8 < 8; r8++) {
            int row = wid * 8 + r8;
            float4 v = ((const float4*)(rel + (size_t)row * EDIM))[lane];
            float ss = v.x * v.x + v.y * v.y + v.z * v.z + v.w * v.w;
            #pragma unroll
            for (int o = 16; o; o >>= 1) ss += __shfl_xor_sync(0xffffffffu, ss, o);
            float n = sqrtf(ss);
            float s = fminf(1.0f, 1.0f / fmaxf(n, 1e-12f));
            ((float4*)(g_RelN + (size_t)row * EDIM))[lane] =
                make_float4(v.x * s, v.y * s, v.z * s, v.w * s);
        }
    }

    if (tid < 128) ((float*)(sm + OFF_BIAS))[tid] = bias[tid];

    // A prologue: load raw ent rows, row-maxnorm; store SCALE (4B/row) instead of EntN
    #pragma unroll
    for (int i = 0; i < 8; i++) {
        int g = tid + i * 256;
        int row = g >> 4, c8 = g & 15, col0 = c8 * 8;
        float4 v0 = make_float4(0.f, 0.f, 0.f, 0.f), v1 = v0;
        if (row < rows_valid) {
            const float4* p = (const float4*)(ent + (size_t)(m0 + row) * EDIM) + c8 * 2;
            v0 = p[0];
            v1 = p[1];
        }
        float ss = v0.x * v0.x + v0.y * v0.y + v0.z * v0.z + v0.w * v0.w +
                   v1.x * v1.x + v1.y * v1.y + v1.z * v1.z + v1.w * v1.w;
        #pragma unroll
        for (int o = 8; o; o >>= 1) ss += __shfl_xor_sync(0xffffffffu, ss, o);
        float n = sqrtf(ss);
        float s = fminf(1.0f, 1.0f / fmaxf(n, 1e-12f));
        if (row < rows_valid && c8 == 0) g_Scale[m0 + row] = s;
        float f[8] = {v0.x * s, v0.y * s, v0.z * s, v0.w * s,
                      v1.x * s, v1.y * s, v1.z * s, v1.w * s};
        __nv_bfloat16 h[8];
        #pragma unroll
        for (int j = 0; j < 8; j++) h[j] = __float2bfloat16(f[j]);
        uint4 hv = make_uint4(pk_bf2(h[0], h[1]), pk_bf2(h[2], h[3]),
                              pk_bf2(h[4], h[5]), pk_bf2(h[6], h[7]));
        *(uint4*)(sm + OFF_AH + (size_t)row * LDT * 2 + col0 * 2) = hv;
    }

    load_hi(Wr, sm, OFF_BH1, tid);
    __syncthreads();

    int rowA  = wy * 64 + (lane & 15);
    int colA  = (lane >> 4) * 8;
    int nrow  = wx * 32 + (lane & 7) + ((lane >> 4) ? 8 : 0);
    int kaddB = ((lane >> 3) & 1) * 8;

    uint32_t aB = smb + OFF_AH, bB = smb + OFF_BH1;

    float d[4][4][4];
    #pragma unroll
    for (int i = 0; i < 4; i++)
        #pragma unroll
        for (int j = 0; j < 4; j++)
            #pragma unroll
            for (int q = 0; q < 4; q++) d[i][j][q] = 0.f;

    #pragma unroll
    for (int ks = 0; ks < 8; ks++) {
        int k0 = ks * 16;
        uint32_t a[4][4];
        #pragma unroll
        for (int mi = 0; mi < 4; mi++) {
            uint32_t addr = aB + (uint32_t)(((rowA + mi * 16) * LDT + k0 + colA) * 2);
            ldmx4(a[mi][0], a[mi][1], a[mi][2], a[mi][3], addr);
        }
        uint32_t b[4][2];
        #pragma unroll
        for (int nj2 = 0; nj2 < 2; nj2++) {
            uint32_t addr = bB + (uint32_t)(((nrow + nj2 * 16) * LDT + k0 + kaddB) * 2);
            uint32_t r0, r1, r2, r3;
            ldmx4(r0, r1, r2, r3, addr);
            b[nj2 * 2 + 0][0] = r0; b[nj2 * 2 + 0][1] = r1;
            b[nj2 * 2 + 1][0] = r2; b[nj2 * 2 + 1][1] = r3;
        }
        #pragma unroll
        for (int mi = 0; mi < 4; mi++)
            #pragma unroll
            for (int nj = 0; nj < 4; nj++)
                mma_bf16(d[mi][nj], a[mi], b[nj]);
    }

    const float* sb = (const float*)(sm + OFF_BIAS);
    int qrow = lane >> 2, qcol = (lane & 3) * 2;
    #pragma unroll
    for (int mi = 0; mi < 4; mi++) {
        #pragma unroll
        for (int half = 0; half < 2; half++) {
            int gm = m0 + wy * 64 + mi * 16 + qrow + half * 8;
            if (gm < M) {
                #pragma unroll
                for (int nj = 0; nj < 4; nj++) {
                    int gc = wx * 32 + nj * 8 + qcol;
                    float x0 = d[mi][nj][half * 2 + 0] + sb[gc];
                    float x1 = d[mi][nj][half * 2 + 1] + sb[gc + 1];
                    *(uint32_t*)(C + (size_t)gm * 128 + gc) =
                        pk_bf2(__float2bfloat16(x0), __float2bfloat16(x1));
                }
            }
        }
    }
}

// ---------------- k_main: attention; gathers raw ent, scale folded into att ----------
__global__ __launch_bounds__(128) void k_main(const int* __restrict__ idx,
                                              const int* __restrict__ adj_ent,
                                              const int* __restrict__ adj_rel,
                                              const float* __restrict__ ent) {
    __shared__ __align__(16) float s_hr[128];
    __shared__ __align__(16) float s_h[128];
    __shared__ float s_sc[32];
    __shared__ float s_att[32];
    __shared__ float s_esc[32];
    __shared__ int   s_eid[32];
    __shared__ int   s_rid[32];

    int b   = blockIdx.x;
    int tid = threadIdx.x;

    int ib = idx[b];
    ib = min(max(ib, 0), N_ENTS - 1);

    if (tid < 32) {
        int e = adj_ent[(size_t)ib * KNBR + tid];
        e = min(max(e, 0), N_ENTS - 1);
        s_eid[tid] = e;
        s_esc[tid] = g_Scale[e];
        int r = adj_rel[(size_t)ib * KNBR + tid];
        s_rid[tid] = min(max(r, 0), N_RELS - 1);
    }
    float s_ib = g_Scale[ib];   // broadcast load (all threads, same address)
    s_hr[tid] = __bfloat162float(g_TrTb[(size_t)ib * EDIM + tid]);
    s_h[tid]  = ent[(size_t)ib * EDIM + tid] * s_ib;
    __syncthreads();

    int w = tid >> 5, l = tid & 31;
    float4 hr4 = *(const float4*)(s_hr + l * 4);

    #pragma unroll
    for (int kk = 0; kk < 8; kk++) {
        int k = w * 8 + kk;
        int e = s_eid[k], r = s_rid[k];
        uint2 trb = *(const uint2*)(g_TrTb + (size_t)e * EDIM + l * 4);
        float2 t01 = __bfloat1622float2(*(const __nv_bfloat162*)&trb.x);
        float2 t23 = __bfloat1622float2(*(const __nv_bfloat162*)&trb.y);
        float4 rv = *(const float4*)(g_RelN + (size_t)r * EDIM + l * 4);
        float p = tanh_hw(hr4.x + rv.x) * t01.x + tanh_hw(hr4.y + rv.y) * t01.y +
                  tanh_hw(hr4.z + rv.z) * t23.x + tanh_hw(hr4.w + rv.w) * t23.y;
        #pragma unroll
        for (int o = 16; o; o >>= 1) p += __shfl_xor_sync(0xffffffffu, p, o);
        if (l == 0) s_sc[k] = p;
    }
    __syncthreads();

    if (tid < 32) {
        float sc = s_sc[tid];
        float mx = sc;
        #pragma unroll
        for (int o = 16; o; o >>= 1) mx = fmaxf(mx, __shfl_xor_sync(0xffffffffu, mx, o));
        float ex = __expf(sc - mx);
        float sum = ex;
        #pragma unroll
        for (int o = 16; o; o >>= 1) sum += __shfl_xor_sync(0xffffffffu, sum, o);
        // fold the neighbor's maxnorm scale into its attention weight:
        // att_k * (s_k * ent[e_k]) == (att_k * s_k) * ent[e_k]
        s_att[tid] = (ex / sum) * s_esc[tid];
    }
    __syncthreads();

    float acc = 0.f;
    #pragma unroll
    for (int k = 0; k < KNBR; k++)
        acc = fmaf(s_att[k], ent[(size_t)s_eid[k] * EDIM + tid], acc);

    float hv = s_h[tid];
    float x1 = hv + acc, x2 = hv * acc;
    size_t o = (size_t)b * EDIM + tid;
    __nv_bfloat16 h1 = __float2bfloat16(x1);
    g_X1h[o] = h1;
    g_X1l[o] = __float2bfloat16(x1 - __bfloat162float(h1));
    __nv_bfloat16 h2 = __float2bfloat16(x2);
    g_X2h[o] = h2;
    g_X2l[o] = __float2bfloat16(x2 - __bfloat162float(h2));
}

// ------- fused output with cp.async pipeline (round-11/13 proven) --------------------
__device__ __forceinline__ void gemm_half(uint32_t smb, int aHoff, int aLoff,
                                          int bHoff, int bLoff,
                                          int rowA, int colA, int nrow, int kaddB,
                                          float d[2][4][4]) {
    #pragma unroll
    for (int ks = 0; ks < 8; ks++) {
        int k0 = ks * 16;
        #pragma unroll
        for (int pass = 0; pass < 3; pass++) {
            uint32_t aB = smb + ((pass == 2) ? aLoff : aHoff);
            uint32_t bB = smb + ((pass == 1) ? bLoff : bHoff);
            uint32_t a[2][4];
            #pragma unroll
            for (int mi = 0; mi < 2; mi++) {
                uint32_t addr = aB + (uint32_t)(((rowA + mi * 16) * LDT + k0 + colA) * 2);
                ldmx4(a[mi][0], a[mi][1], a[mi][2], a[mi][3], addr);
            }
            uint32_t b[4][2];
            #pragma unroll
            for (int nj2 = 0; nj2 < 2; nj2++) {
                uint32_t addr = bB + (uint32_t)(((nrow + nj2 * 16) * LDT + k0 + kaddB) * 2);
                uint32_t r0, r1, r2, r3;
                ldmx4(r0, r1, r2, r3, addr);
                b[nj2 * 2 + 0][0] = r0; b[nj2 * 2 + 0][1] = r1;
                b[nj2 * 2 + 1][0] = r2; b[nj2 * 2 + 1][1] = r3;
            }
            #pragma unroll
            for (int mi = 0; mi < 2; mi++)
                #pragma unroll
                for (int nj = 0; nj < 4; nj++)
                    mma_bf16(d[mi][nj], a[mi], b[nj]);
        }
    }
}

__global__ __launch_bounds__(256, 1) void k_out_fused(const float* __restrict__ W1,
                                                      const float* __restrict__ b1,
                                                      const float* __restrict__ W2,
                                                      const float* __restrict__ b2,
                                                      float* __restrict__ C, int M) {
    extern __shared__ char sm[];
    uint32_t smb = smem_u32(sm);
    int tid  = threadIdx.x;
    int wid  = tid >> 5, lane = tid & 31;
    int wy   = wid >> 1, wx = wid & 1;
    int m0   = blockIdx.x * 128;
    int n0   = blockIdx.y * 64;

    size_t aoff = (size_t)m0 * EDIM;
    copy128_async(g_X1h + aoff, smb, OA1H, tid);
    copy128_async(g_X1l + aoff, smb, OA1L, tid);
    CP_COMMIT();
    copy128_async(g_X2h + aoff, smb, OA2H, tid);
    copy128_async(g_X2l + aoff, smb, OA2L, tid);
    CP_COMMIT();

    if (tid < 64) {
        ((float*)(sm + OFF_B1))[tid] = b1[n0 + tid];
        ((float*)(sm + OFF_B2))[tid] = b2[n0 + tid];
    }
    load_split64(W1 + (size_t)n0 * EDIM, sm, OW1H, OW1L, tid);
    load_split64(W2 + (size_t)n0 * EDIM, sm, OW2H, OW2L, tid);

    int rowA  = wy * 32 + (lane & 15);
    int colA  = (lane >> 4) * 8;
    int nrow  = wx * 32 + (lane & 7) + ((lane >> 4) ? 8 : 0);
    int kaddB = ((lane >> 3) & 1) * 8;

    float d1[2][4][4], d2[2][4][4];
    #pragma unroll
    for (int i = 0; i < 2; i++)
        #pragma unroll
        for (int j = 0; j < 4; j++)
            #pragma unroll
            for (int q = 0; q < 4; q++) { d1[i][j][q] = 0.f; d2[i][j][q] = 0.f; }

    CP_WAIT(1);
    __syncthreads();
    gemm_half(smb, OA1H, OA1L, OW1H, OW1L, rowA, colA, nrow, kaddB, d1);

    CP_WAIT(0);
    __syncthreads();
    gemm_half(smb, OA2H, OA2L, OW2H, OW2L, rowA, colA, nrow, kaddB, d2);

    const float* sb1 = (const float*)(sm + OFF_B1);
    const float* sb2 = (const float*)(sm + OFF_B2);
    int qrow = lane >> 2, qcol = (lane & 3) * 2;
    #pragma unroll
    for (int mi = 0; mi < 2; mi++) {
        #pragma unroll
        for (int half = 0; half < 2; half++) {
            int gm = m0 + wy * 32 + mi * 16 + qrow + half * 8;
            #pragma unroll
            for (int nj = 0; nj < 4; nj++) {
                int gc = wx * 32 + nj * 8 + qcol;
                float u0 = d1[mi][nj][half * 2 + 0] + sb1[gc];
                float u1 = d1[mi][nj][half * 2 + 1] + sb1[gc + 1];
                float v0 = d2[mi][nj][half * 2 + 0] + sb2[gc];
                float v1 = d2[mi][nj][half * 2 + 1] + sb2[gc + 1];
                u0 = (u0 > 0.f) ? u0 : 0.2f * u0;
                u1 = (u1 > 0.f) ? u1 : 0.2f * u1;
                v0 = (v0 > 0.f) ? v0 : 0.2f * v0;
                v1 = (v1 > 0.f) ? v1 : 0.2f * v1;
                *(float2*)(C + (size_t)gm * 128 + n0 + gc) = make_float2(u0 + v0, u1 + v1);
            }
        }
    }
}

// ---------------- launch ---------------------------------------------------------------
extern "C" void kernel_launch(void* const* d_in, const int* in_sizes, int n_in,
                              void* d_out, int out_size) {
    const int*   idx     = (const int*)d_in[0];
    const int*   adj_ent = (const int*)d_in[1];
    const int*   adj_rel = (const int*)d_in[2];
    const float* ent     = (const float*)d_in[3];
    const float* rel     = (const float*)d_in[4];
    const float* Wr_w    = (const float*)d_in[5];
    const float* Wr_b    = (const float*)d_in[6];
    const float* W1_w    = (const float*)d_in[7];
    const float* W1_b    = (const float*)d_in[8];
    const float* W2_w    = (const float*)d_in[9];
    const float* W2_b    = (const float*)d_in[10];
    float* out = (float*)d_out;

    cudaFuncSetAttribute(k_trt_fused, cudaFuncAttributeMaxDynamicSharedMemorySize, SMEM_TRT);
    cudaFuncSetAttribute(k_out_fused, cudaFuncAttributeMaxDynamicSharedMemorySize, SMEM_OUT);

    __nv_bfloat16* TrTb;
    cudaGetSymbolAddress((void**)&TrTb, g_TrTb);

    k_trt_fused<<<(N_ENTS + 127) / 128, 256, SMEM_TRT>>>(ent, rel, Wr_w, Wr_b, TrTb, N_ENTS);
    k_main<<<BATCH, 128>>>(idx, adj_ent, adj_rel, ent);
    dim3 go(BATCH / 128, 2);
    k_out_fused<<<go, 256, SMEM_OUT>>>(W1_w, W1_b, W2_w, W2_b, out, BATCH);
}

// round 15
// speedup vs baseline: 1.2696x; 1.0693x over previous
#include <cuda_runtime.h>
#include <cuda_bf16.h>
#include <math.h>
#include <stdint.h>

#define N_ENTS  100000
#define N_RELS  64
#define EDIM    128
#define KNBR    32
#define BATCH   16384

// ---------------- device-global scratch ------------------------------------------
__device__ float         g_Scale[N_ENTS];                 // per-row maxnorm scale
__device__ __nv_bfloat16 g_EntNb[(size_t)N_ENTS * EDIM];  // bf16(maxnorm(ent))
__device__ __nv_bfloat16 g_TrTb[(size_t)N_ENTS * EDIM];   // bf16(maxnorm(ent) @ Wr^T + b)
__device__ float         g_RelN[(size_t)N_RELS * EDIM];
__device__ __nv_bfloat16 g_X1h[(size_t)BATCH * EDIM];
__device__ __nv_bfloat16 g_X1l[(size_t)BATCH * EDIM];
__device__ __nv_bfloat16 g_X2h[(size_t)BATCH * EDIM];
__device__ __nv_bfloat16 g_X2l[(size_t)BATCH * EDIM];

// ---------------- helpers ----------------------------------------------------------
__device__ __forceinline__ uint32_t smem_u32(const void* p) {
    uint32_t a;
    asm("{ .reg .u64 t; cvta.to.shared.u64 t, %1; cvt.u32.u64 %0, t; }" : "=r"(a) : "l"(p));
    return a;
}
__device__ __forceinline__ void ldmx4(uint32_t& r0, uint32_t& r1, uint32_t& r2, uint32_t& r3,
                                      uint32_t addr) {
    asm volatile("ldmatrix.sync.aligned.m8n8.x4.shared.b16 {%0,%1,%2,%3}, [%4];"
                 : "=r"(r0), "=r"(r1), "=r"(r2), "=r"(r3) : "r"(addr));
}
__device__ __forceinline__ void mma_bf16(float* d, const uint32_t* a, const uint32_t* b) {
    asm volatile(
        "mma.sync.aligned.m16n8k16.row.col.f32.bf16.bf16.f32 "
        "{%0,%1,%2,%3}, {%4,%5,%6,%7}, {%8,%9}, {%0,%1,%2,%3};"
        : "+f"(d[0]), "+f"(d[1]), "+f"(d[2]), "+f"(d[3])
        : "r"(a[0]), "r"(a[1]), "r"(a[2]), "r"(a[3]), "r"(b[0]), "r"(b[1]));
}
__device__ __forceinline__ uint32_t pk_bf2(__nv_bfloat16 a, __nv_bfloat16 b) {
    __nv_bfloat162 t(a, b);
    return *(uint32_t*)&t;
}
__device__ __forceinline__ float tanh_hw(float x) {
    float y;
    asm("tanh.approx.f32 %0, %1;" : "=f"(y) : "f"(x));
    return y;
}
__device__ __forceinline__ void cp16(uint32_t dst, const void* src) {
    asm volatile("cp.async.cg.shared.global [%0], [%1], 16;" :: "r"(dst), "l"(src));
}
#define CP_COMMIT() asm volatile("cp.async.commit_group;" ::: "memory")
#define CP_WAIT(n)  asm volatile("cp.async.wait_group %0;" :: "n"(n) : "memory")

// padded bf16 tiles, row stride 136 elems (272 B) -> conflict-free ldmatrix
#define LDT 136
#define TILE_B  (128 * LDT * 2)   // 34816
#define HTILE_B (64  * LDT * 2)   // 17408
// TrT kernel layout
#define OFF_BIAS 0
#define OFF_AH   512
#define OFF_BH1  (512 + TILE_B)
#define SMEM_TRT (512 + 2 * TILE_B)              // 70,144 -> 2 CTAs/SM
// fused output kernel layout
#define OFF_B1   0
#define OFF_B2   256
#define OA1H     512
#define OA1L     (512 + TILE_B)
#define OA2H     (512 + 2 * TILE_B)
#define OA2L     (512 + 3 * TILE_B)
#define OW1H     (512 + 4 * TILE_B)
#define OW1L     (512 + 4 * TILE_B + HTILE_B)
#define OW2H     (512 + 4 * TILE_B + 2 * HTILE_B)
#define OW2L     (512 + 4 * TILE_B + 3 * HTILE_B)
#define SMEM_OUT (512 + 4 * TILE_B + 4 * HTILE_B)   // 209,408 -> 1 CTA/SM

// async bf16 tile copy: gmem (stride 128) -> padded smem, 128 rows
__device__ __forceinline__ void copy128_async(const __nv_bfloat16* __restrict__ src,
                                              uint32_t smb, int off, int tid) {
    #pragma unroll
    for (int i = 0; i < 8; i++) {
        int g = tid + i * 256;
        int row = g >> 4, c8 = g & 15;
        cp16(smb + off + row * LDT * 2 + c8 * 16, src + (size_t)row * EDIM + c8 * 8);
    }
}
// fp32 -> bf16 hi/lo split, 64 rows
__device__ __forceinline__ void load_split64(const float* __restrict__ src,
                                             char* sm, int off_h, int off_l, int tid) {
    #pragma unroll
    for (int i = 0; i < 4; i++) {
        int g = tid + i * 256;
        int row = g >> 4, c8 = g & 15, col0 = c8 * 8;
        const float4* p = (const float4*)src + (size_t)row * 32 + c8 * 2;
        float4 v0 = p[0], v1 = p[1];
        float f[8] = {v0.x, v0.y, v0.z, v0.w, v1.x, v1.y, v1.z, v1.w};
        __nv_bfloat16 h[8], l[8];
        #pragma unroll
        for (int j = 0; j < 8; j++) {
            h[j] = __float2bfloat16(f[j]);
            l[j] = __float2bfloat16(f[j] - __bfloat162float(h[j]));
        }
        uint4 hv = make_uint4(pk_bf2(h[0], h[1]), pk_bf2(h[2], h[3]),
                              pk_bf2(h[4], h[5]), pk_bf2(h[6], h[7]));
        uint4 lv = make_uint4(pk_bf2(l[0], l[1]), pk_bf2(l[2], l[3]),
                              pk_bf2(l[4], l[5]), pk_bf2(l[6], l[7]));
        size_t o = (size_t)row * LDT * 2 + col0 * 2;
        *(uint4*)(sm + off_h + o) = hv;
        *(uint4*)(sm + off_l + o) = lv;
    }
}
// hi-only fp32->bf16, 128 rows
__device__ __forceinline__ void load_hi(const float* __restrict__ src,
                                        char* sm, int off_h, int tid) {
    #pragma unroll
    for (int i = 0; i < 8; i++) {
        int g = tid + i * 256;
        int row = g >> 4, c8 = g & 15, col0 = c8 * 8;
        const float4* p = (const float4*)src + (size_t)row * 32 + c8 * 2;
        float4 v0 = p[0], v1 = p[1];
        float f[8] = {v0.x, v0.y, v0.z, v0.w, v1.x, v1.y, v1.z, v1.w};
        __nv_bfloat16 h[8];
        #pragma unroll
        for (int j = 0; j < 8; j++) h[j] = __float2bfloat16(f[j]);
        uint4 hv = make_uint4(pk_bf2(h[0], h[1]), pk_bf2(h[2], h[3]),
                              pk_bf2(h[4], h[5]), pk_bf2(h[6], h[7]));
        *(uint4*)(sm + off_h + (size_t)row * LDT * 2 + col0 * 2) = hv;
    }
}

// ---------- fused: rel-norm + ent maxnorm -> scale + EntNb + 1-pass GEMM -> TrTb -----
__global__ __launch_bounds__(256, 2) void k_trt_fused(const float* __restrict__ ent,
                                                      const float* __restrict__ rel,
                                                      const float* __restrict__ Wr,
                                                      const float* __restrict__ bias,
                                                      __nv_bfloat16* __restrict__ C,
                                                      int M) {
    extern __shared__ char sm[];
    uint32_t smb = smem_u32(sm);
    int tid  = threadIdx.x;
    int wid  = tid >> 5, lane = tid & 31;
    int wy   = wid >> 2, wx = wid & 3;
    int m0   = blockIdx.x * 128;
    int rows_valid = M - m0;

    // block 0 additionally normalizes the 64-row rel table (warp-per-row)
    if (blockIdx.x == 0) {
        #pragma unroll
        for (int r8 = 0; r8 < 8; r8++) {
            int row = wid * 8 + r8;
            float4 v = ((const float4*)(rel + (size_t)row * EDIM))[lane];
            float ss = v.x * v.x + v.y * v.y + v.z * v.z + v.w * v.w;
            #pragma unroll
            for (int o = 16; o; o >>= 1) ss += __shfl_xor_sync(0xffffffffu, ss, o);
            float n = sqrtf(ss);
            float s = fminf(1.0f, 1.0f / fmaxf(n, 1e-12f));
            ((float4*)(g_RelN + (size_t)row * EDIM))[lane] =
                make_float4(v.x * s, v.y * s, v.z * s, v.w * s);
        }
    }

    if (tid < 128) ((float*)(sm + OFF_BIAS))[tid] = bias[tid];

    // A prologue: raw ent rows -> maxnorm; emit scale (4B/row) + EntNb (bf16) + smem Ah
    #pragma unroll
    for (int i = 0; i < 8; i++) {
        int g = tid + i * 256;
        int row = g >> 4, c8 = g & 15, col0 = c8 * 8;
        float4 v0 = make_float4(0.f, 0.f, 0.f, 0.f), v1 = v0;
        if (row < rows_valid) {
            const float4* p = (const float4*)(ent + (size_t)(m0 + row) * EDIM) + c8 * 2;
            v0 = p[0];
            v1 = p[1];
        }
        float ss = v0.x * v0.x + v0.y * v0.y + v0.z * v0.z + v0.w * v0.w +
                   v1.x * v1.x + v1.y * v1.y + v1.z * v1.z + v1.w * v1.w;
        #pragma unroll
        for (int o = 8; o; o >>= 1) ss += __shfl_xor_sync(0xffffffffu, ss, o);
        float n = sqrtf(ss);
        float s = fminf(1.0f, 1.0f / fmaxf(n, 1e-12f));
        if (row < rows_valid && c8 == 0) g_Scale[m0 + row] = s;
        float f[8] = {v0.x * s, v0.y * s, v0.z * s, v0.w * s,
                      v1.x * s, v1.y * s, v1.z * s, v1.w * s};
        __nv_bfloat16 h[8];
        #pragma unroll
        for (int j = 0; j < 8; j++) h[j] = __float2bfloat16(f[j]);
        uint4 hv = make_uint4(pk_bf2(h[0], h[1]), pk_bf2(h[2], h[3]),
                              pk_bf2(h[4], h[5]), pk_bf2(h[6], h[7]));
        if (row < rows_valid)
            *(uint4*)(g_EntNb + (size_t)(m0 + row) * EDIM + col0) = hv;
        *(uint4*)(sm + OFF_AH + (size_t)row * LDT * 2 + col0 * 2) = hv;
    }

    load_hi(Wr, sm, OFF_BH1, tid);
    __syncthreads();

    int rowA  = wy * 64 + (lane & 15);
    int colA  = (lane >> 4) * 8;
    int nrow  = wx * 32 + (lane & 7) + ((lane >> 4) ? 8 : 0);
    int kaddB = ((lane >> 3) & 1) * 8;

    uint32_t aB = smb + OFF_AH, bB = smb + OFF_BH1;

    float d[4][4][4];
    #pragma unroll
    for (int i = 0; i < 4; i++)
        #pragma unroll
        for (int j = 0; j < 4; j++)
            #pragma unroll
            for (int q = 0; q < 4; q++) d[i][j][q] = 0.f;

    #pragma unroll
    for (int ks = 0; ks < 8; ks++) {
        int k0 = ks * 16;
        uint32_t a[4][4];
        #pragma unroll
        for (int mi = 0; mi < 4; mi++) {
            uint32_t addr = aB + (uint32_t)(((rowA + mi * 16) * LDT + k0 + colA) * 2);
            ldmx4(a[mi][0], a[mi][1], a[mi][2], a[mi][3], addr);
        }
        uint32_t b[4][2];
        #pragma unroll
        for (int nj2 = 0; nj2 < 2; nj2++) {
            uint32_t addr = bB + (uint32_t)(((nrow + nj2 * 16) * LDT + k0 + kaddB) * 2);
            uint32_t r0, r1, r2, r3;
            ldmx4(r0, r1, r2, r3, addr);
            b[nj2 * 2 + 0][0] = r0; b[nj2 * 2 + 0][1] = r1;
            b[nj2 * 2 + 1][0] = r2; b[nj2 * 2 + 1][1] = r3;
        }
        #pragma unroll
        for (int mi = 0; mi < 4; mi++)
            #pragma unroll
            for (int nj = 0; nj < 4; nj++)
                mma_bf16(d[mi][nj], a[mi], b[nj]);
    }

    const float* sb = (const float*)(sm + OFF_BIAS);
    int qrow = lane >> 2, qcol = (lane & 3) * 2;
    #pragma unroll
    for (int mi = 0; mi < 4; mi++) {
        #pragma unroll
        for (int half = 0; half < 2; half++) {
            int gm = m0 + wy * 64 + mi * 16 + qrow + half * 8;
            if (gm < M) {
                #pragma unroll
                for (int nj = 0; nj < 4; nj++) {
                    int gc = wx * 32 + nj * 8 + qcol;
                    float x0 = d[mi][nj][half * 2 + 0] + sb[gc];
                    float x1 = d[mi][nj][half * 2 + 1] + sb[gc + 1];
                    *(uint32_t*)(C + (size_t)gm * 128 + gc) =
                        pk_bf2(__float2bfloat16(x0), __float2bfloat16(x1));
                }
            }
        }
    }
}

// ---------------- k_main: attention; Nh gathers EntNb (bf16), h stays fp32 -----------
__global__ __launch_bounds__(128) void k_main(const int* __restrict__ idx,
                                              const int* __restrict__ adj_ent,
                                              const int* __restrict__ adj_rel,
                                              const float* __restrict__ ent) {
    __shared__ __align__(16) float s_hr[128];
    __shared__ __align__(16) float s_h[128];
    __shared__ float s_sc[32];
    __shared__ float s_att[32];
    __shared__ int   s_eid[32];
    __shared__ int   s_rid[32];

    int b   = blockIdx.x;
    int tid = threadIdx.x;

    int ib = idx[b];
    ib = min(max(ib, 0), N_ENTS - 1);

    if (tid < 32) {
        int e = adj_ent[(size_t)ib * KNBR + tid];
        s_eid[tid] = min(max(e, 0), N_ENTS - 1);
        int r = adj_rel[(size_t)ib * KNBR + tid];
        s_rid[tid] = min(max(r, 0), N_RELS - 1);
    }
    float s_ib = g_Scale[ib];   // broadcast load
    s_hr[tid] = __bfloat162float(g_TrTb[(size_t)ib * EDIM + tid]);
    s_h[tid]  = ent[(size_t)ib * EDIM + tid] * s_ib;   // h in full fp32
    __syncthreads();

    int w = tid >> 5, l = tid & 31;
    float4 hr4 = *(const float4*)(s_hr + l * 4);

    #pragma unroll
    for (int kk = 0; kk < 8; kk++) {
        int k = w * 8 + kk;
        int e = s_eid[k], r = s_rid[k];
        uint2 trb = *(const uint2*)(g_TrTb + (size_t)e * EDIM + l * 4);
        float2 t01 = __bfloat1622float2(*(const __nv_bfloat162*)&trb.x);
        float2 t23 = __bfloat1622float2(*(const __nv_bfloat162*)&trb.y);
        float4 rv = *(const float4*)(g_RelN + (size_t)r * EDIM + l * 4);
        float p = tanh_hw(hr4.x + rv.x) * t01.x + tanh_hw(hr4.y + rv.y) * t01.y +
                  tanh_hw(hr4.z + rv.z) * t23.x + tanh_hw(hr4.w + rv.w) * t23.y;
        #pragma unroll
        for (int o = 16; o; o >>= 1) p += __shfl_xor_sync(0xffffffffu, p, o);
        if (l == 0) s_sc[k] = p;
    }
    __syncthreads();

    if (tid < 32) {
        float sc = s_sc[tid];
        float mx = sc;
        #pragma unroll
        for (int o = 16; o; o >>= 1) mx = fmaxf(mx, __shfl_xor_sync(0xffffffffu, mx, o));
        float ex = __expf(sc - mx);
        float sum = ex;
        #pragma unroll
        for (int o = 16; o; o >>= 1) sum += __shfl_xor_sync(0xffffffffu, sum, o);
        s_att[tid] = ex / sum;
    }
    __syncthreads();

    // Nh from bf16 normalized rows (half the gather bytes of fp32)
    float acc = 0.f;
    #pragma unroll
    for (int k = 0; k < KNBR; k++)
        acc = fmaf(s_att[k],
                   __bfloat162float(g_EntNb[(size_t)s_eid[k] * EDIM + tid]), acc);

    float hv = s_h[tid];
    float x1 = hv + acc, x2 = hv * acc;
    size_t o = (size_t)b * EDIM + tid;
    __nv_bfloat16 h1 = __float2bfloat16(x1);
    g_X1h[o] = h1;
    g_X1l[o] = __float2bfloat16(x1 - __bfloat162float(h1));
    __nv_bfloat16 h2 = __float2bfloat16(x2);
    g_X2h[o] = h2;
    g_X2l[o] = __float2bfloat16(x2 - __bfloat162float(h2));
}

// ------- fused output with cp.async pipeline (round-11/13 proven) --------------------
__device__ __forceinline__ void gemm_half(uint32_t smb, int aHoff, int aLoff,
                                          int bHoff, int bLoff,
                                          int rowA, int colA, int nrow, int kaddB,
                                          float d[2][4][4]) {
    #pragma unroll
    for (int ks = 0; ks < 8; ks++) {
        int k0 = ks * 16;
        #pragma unroll
        for (int pass = 0; pass < 3; pass++) {
            uint32_t aB = smb + ((pass == 2) ? aLoff : aHoff);
            uint32_t bB = smb + ((pass == 1) ? bLoff : bHoff);
            uint32_t a[2][4];
            #pragma unroll
            for (int mi = 0; mi < 2; mi++) {
                uint32_t addr = aB + (uint32_t)(((rowA + mi * 16) * LDT + k0 + colA) * 2);
                ldmx4(a[mi][0], a[mi][1], a[mi][2], a[mi][3], addr);
            }
            uint32_t b[4][2];
            #pragma unroll
            for (int nj2 = 0; nj2 < 2; nj2++) {
                uint32_t addr = bB + (uint32_t)(((nrow + nj2 * 16) * LDT + k0 + kaddB) * 2);
                uint32_t r0, r1, r2, r3;
                ldmx4(r0, r1, r2, r3, addr);
                b[nj2 * 2 + 0][0] = r0; b[nj2 * 2 + 0][1] = r1;
                b[nj2 * 2 + 1][0] = r2; b[nj2 * 2 + 1][1] = r3;
            }
            #pragma unroll
            for (int mi = 0; mi < 2; mi++)
                #pragma unroll
                for (int nj = 0; nj < 4; nj++)
                    mma_bf16(d[mi][nj], a[mi], b[nj]);
        }
    }
}

__global__ __launch_bounds__(256, 1) void k_out_fused(const float* __restrict__ W1,
                                                      const float* __restrict__ b1,
                                                      const float* __restrict__ W2,
                                                      const float* __restrict__ b2,
                                                      float* __restrict__ C, int M) {
    extern __shared__ char sm[];
    uint32_t smb = smem_u32(sm);
    int tid  = threadIdx.x;
    int wid  = tid >> 5, lane = tid & 31;
    int wy   = wid >> 1, wx = wid & 1;
    int m0   = blockIdx.x * 128;
    int n0   = blockIdx.y * 64;

    size_t aoff = (size_t)m0 * EDIM;
    copy128_async(g_X1h + aoff, smb, OA1H, tid);
    copy128_async(g_X1l + aoff, smb, OA1L, tid);
    CP_COMMIT();
    copy128_async(g_X2h + aoff, smb, OA2H, tid);
    copy128_async(g_X2l + aoff, smb, OA2L, tid);
    CP_COMMIT();

    if (tid < 64) {
        ((float*)(sm + OFF_B1))[tid] = b1[n0 + tid];
        ((float*)(sm + OFF_B2))[tid] = b2[n0 + tid];
    }
    load_split64(W1 + (size_t)n0 * EDIM, sm, OW1H, OW1L, tid);
    load_split64(W2 + (size_t)n0 * EDIM, sm, OW2H, OW2L, tid);

    int rowA  = wy * 32 + (lane & 15);
    int colA  = (lane >> 4) * 8;
    int nrow  = wx * 32 + (lane & 7) + ((lane >> 4) ? 8 : 0);
    int kaddB = ((lane >> 3) & 1) * 8;

    float d1[2][4][4], d2[2][4][4];
    #pragma unroll
    for (int i = 0; i < 2; i++)
        #pragma unroll
        for (int j = 0; j < 4; j++)
            #pragma unroll
            for (int q = 0; q < 4; q++) { d1[i][j][q] = 0.f; d2[i][j][q] = 0.f; }

    CP_WAIT(1);
    __syncthreads();
    gemm_half(smb, OA1H, OA1L, OW1H, OW1L, rowA, colA, nrow, kaddB, d1);

    CP_WAIT(0);
    __syncthreads();
    gemm_half(smb, OA2H, OA2L, OW2H, OW2L, rowA, colA, nrow, kaddB, d2);

    const float* sb1 = (const float*)(sm + OFF_B1);
    const float* sb2 = (const float*)(sm + OFF_B2);
    int qrow = lane >> 2, qcol = (lane & 3) * 2;
    #pragma unroll
    for (int mi = 0; mi < 2; mi++) {
        #pragma unroll
        for (int half = 0; half < 2; half++) {
            int gm = m0 + wy * 32 + mi * 16 + qrow + half * 8;
            #pragma unroll
            for (int nj = 0; nj < 4; nj++) {
                int gc = wx * 32 + nj * 8 + qcol;
                float u0 = d1[mi][nj][half * 2 + 0] + sb1[gc];
                float u1 = d1[mi][nj][half * 2 + 1] + sb1[gc + 1];
                float v0 = d2[mi][nj][half * 2 + 0] + sb2[gc];
                float v1 = d2[mi][nj][half * 2 + 1] + sb2[gc + 1];
                u0 = (u0 > 0.f) ? u0 : 0.2f * u0;
                u1 = (u1 > 0.f) ? u1 : 0.2f * u1;
                v0 = (v0 > 0.f) ? v0 : 0.2f * v0;
                v1 = (v1 > 0.f) ? v1 : 0.2f * v1;
                *(float2*)(C + (size_t)gm * 128 + n0 + gc) = make_float2(u0 + v0, u1 + v1);
            }
        }
    }
}

// ---------------- launch ---------------------------------------------------------------
extern "C" void kernel_launch(void* const* d_in, const int* in_sizes, int n_in,
                              void* d_out, int out_size) {
    const int*   idx     = (const int*)d_in[0];
    const int*   adj_ent = (const int*)d_in[1];
    const int*   adj_rel = (const int*)d_in[2];
    const float* ent     = (const float*)d_in[3];
    const float* rel     = (const float*)d_in[4];
    const float* Wr_w    = (const float*)d_in[5];
    const float* Wr_b    = (const float*)d_in[6];
    const float* W1_w    = (const float*)d_in[7];
    const float* W1_b    = (const float*)d_in[8];
    const float* W2_w    = (const float*)d_in[9];
    const float* W2_b    = (const float*)d_in[10];
    float* out = (float*)d_out;

    cudaFuncSetAttribute(k_trt_fused, cudaFuncAttributeMaxDynamicSharedMemorySize, SMEM_TRT);
    cudaFuncSetAttribute(k_out_fused, cudaFuncAttributeMaxDynamicSharedMemorySize, SMEM_OUT);

    __nv_bfloat16* TrTb;
    cudaGetSymbolAddress((void**)&TrTb, g_TrTb);

    k_trt_fused<<<(N_ENTS + 127) / 128, 256, SMEM_TRT>>>(ent, rel, Wr_w, Wr_b, TrTb, N_ENTS);
    k_main<<<BATCH, 128>>>(idx, adj_ent, adj_rel, ent);
    dim3 go(BATCH / 128, 2);
    k_out_fused<<<go, 256, SMEM_OUT>>>(W1_w, W1_b, W2_w, W2_b, out, BATCH);
}

// round 16
// speedup vs baseline: 1.3140x; 1.0350x over previous
#include <cuda_runtime.h>
#include <cuda_bf16.h>
#include <math.h>
#include <stdint.h>

#define N_ENTS  100000
#define N_RELS  64
#define EDIM    128
#define KNBR    32
#define BATCH   16384

// ---------------- device-global scratch ------------------------------------------
__device__ float         g_Scale[N_ENTS];                 // per-row maxnorm scale
__device__ __nv_bfloat16 g_EntNb[(size_t)N_ENTS * EDIM];  // bf16(maxnorm(ent))
__device__ __nv_bfloat16 g_TrTb[(size_t)N_ENTS * EDIM];   // bf16(maxnorm(ent) @ Wr^T + b)
__device__ float         g_RelN[(size_t)N_RELS * EDIM];
__device__ __nv_bfloat16 g_X1h[(size_t)BATCH * EDIM];
__device__ __nv_bfloat16 g_X1l[(size_t)BATCH * EDIM];
__device__ __nv_bfloat16 g_X2h[(size_t)BATCH * EDIM];
__device__ __nv_bfloat16 g_X2l[(size_t)BATCH * EDIM];

// ---------------- helpers ----------------------------------------------------------
__device__ __forceinline__ uint32_t smem_u32(const void* p) {
    uint32_t a;
    asm("{ .reg .u64 t; cvta.to.shared.u64 t, %1; cvt.u32.u64 %0, t; }" : "=r"(a) : "l"(p));
    return a;
}
__device__ __forceinline__ void ldmx4(uint32_t& r0, uint32_t& r1, uint32_t& r2, uint32_t& r3,
                                      uint32_t addr) {
    asm volatile("ldmatrix.sync.aligned.m8n8.x4.shared.b16 {%0,%1,%2,%3}, [%4];"
                 : "=r"(r0), "=r"(r1), "=r"(r2), "=r"(r3) : "r"(addr));
}
__device__ __forceinline__ void mma_bf16(float* d, const uint32_t* a, const uint32_t* b) {
    asm volatile(
        "mma.sync.aligned.m16n8k16.row.col.f32.bf16.bf16.f32 "
        "{%0,%1,%2,%3}, {%4,%5,%6,%7}, {%8,%9}, {%0,%1,%2,%3};"
        : "+f"(d[0]), "+f"(d[1]), "+f"(d[2]), "+f"(d[3])
        : "r"(a[0]), "r"(a[1]), "r"(a[2]), "r"(a[3]), "r"(b[0]), "r"(b[1]));
}
__device__ __forceinline__ uint32_t pk_bf2(__nv_bfloat16 a, __nv_bfloat16 b) {
    __nv_bfloat162 t(a, b);
    return *(uint32_t*)&t;
}
__device__ __forceinline__ float tanh_hw(float x) {
    float y;
    asm("tanh.approx.f32 %0, %1;" : "=f"(y) : "f"(x));
    return y;
}
__device__ __forceinline__ void cp16(uint32_t dst, const void* src) {
    asm volatile("cp.async.cg.shared.global [%0], [%1], 16;" :: "r"(dst), "l"(src));
}
#define CP_COMMIT() asm volatile("cp.async.commit_group;" ::: "memory")
#define CP_WAIT(n)  asm volatile("cp.async.wait_group %0;" :: "n"(n) : "memory")

// padded bf16 tiles, row stride 136 elems (272 B) -> conflict-free ldmatrix
#define LDT 136
#define TILE_B  (128 * LDT * 2)   // 34816
#define HTILE_B (64  * LDT * 2)   // 17408
// TrT kernel layout
#define OFF_BIAS 0
#define OFF_AH   512
#define OFF_BH1  (512 + TILE_B)
#define SMEM_TRT (512 + 2 * TILE_B)              // 70,144 -> 2 CTAs/SM
// fused output kernel layout
#define OFF_B1   0
#define OFF_B2   256
#define OA1H     512
#define OA1L     (512 + TILE_B)
#define OA2H     (512 + 2 * TILE_B)
#define OA2L     (512 + 3 * TILE_B)
#define OW1H     (512 + 4 * TILE_B)
#define OW1L     (512 + 4 * TILE_B + HTILE_B)
#define OW2H     (512 + 4 * TILE_B + 2 * HTILE_B)
#define OW2L     (512 + 4 * TILE_B + 3 * HTILE_B)
#define SMEM_OUT (512 + 4 * TILE_B + 4 * HTILE_B)   // 209,408 -> 1 CTA/SM

// async bf16 tile copy: gmem (stride 128) -> padded smem, 128 rows
__device__ __forceinline__ void copy128_async(const __nv_bfloat16* __restrict__ src,
                                              uint32_t smb, int off, int tid) {
    #pragma unroll
    for (int i = 0; i < 8; i++) {
        int g = tid + i * 256;
        int row = g >> 4, c8 = g & 15;
        cp16(smb + off + row * LDT * 2 + c8 * 16, src + (size_t)row * EDIM + c8 * 8);
    }
}
// fp32 -> bf16 hi/lo split, 64 rows
__device__ __forceinline__ void load_split64(const float* __restrict__ src,
                                             char* sm, int off_h, int off_l, int tid) {
    #pragma unroll
    for (int i = 0; i < 4; i++) {
        int g = tid + i * 256;
        int row = g >> 4, c8 = g & 15, col0 = c8 * 8;
        const float4* p = (const float4*)src + (size_t)row * 32 + c8 * 2;
        float4 v0 = p[0], v1 = p[1];
        float f[8] = {v0.x, v0.y, v0.z, v0.w, v1.x, v1.y, v1.z, v1.w};
        __nv_bfloat16 h[8], l[8];
        #pragma unroll
        for (int j = 0; j < 8; j++) {
            h[j] = __float2bfloat16(f[j]);
            l[j] = __float2bfloat16(f[j] - __bfloat162float(h[j]));
        }
        uint4 hv = make_uint4(pk_bf2(h[0], h[1]), pk_bf2(h[2], h[3]),
                              pk_bf2(h[4], h[5]), pk_bf2(h[6], h[7]));
        uint4 lv = make_uint4(pk_bf2(l[0], l[1]), pk_bf2(l[2], l[3]),
                              pk_bf2(l[4], l[5]), pk_bf2(l[6], l[7]));
        size_t o = (size_t)row * LDT * 2 + col0 * 2;
        *(uint4*)(sm + off_h + o) = hv;
        *(uint4*)(sm + off_l + o) = lv;
    }
}
// hi-only fp32->bf16, 128 rows
__device__ __forceinline__ void load_hi(const float* __restrict__ src,
                                        char* sm, int off_h, int tid) {
    #pragma unroll
    for (int i = 0; i < 8; i++) {
        int g = tid + i * 256;
        int row = g >> 4, c8 = g & 15, col0 = c8 * 8;
        const float4* p = (const float4*)src + (size_t)row * 32 + c8 * 2;
        float4 v0 = p[0], v1 = p[1];
        float f[8] = {v0.x, v0.y, v0.z, v0.w, v1.x, v1.y, v1.z, v1.w};
        __nv_bfloat16 h[8];
        #pragma unroll
        for (int j = 0; j < 8; j++) h[j] = __float2bfloat16(f[j]);
        uint4 hv = make_uint4(pk_bf2(h[0], h[1]), pk_bf2(h[2], h[3]),
                              pk_bf2(h[4], h[5]), pk_bf2(h[6], h[7]));
        *(uint4*)(sm + off_h + (size_t)row * LDT * 2 + col0 * 2) = hv;
    }
}

// ---------- fused: rel-norm + ent maxnorm -> scale + EntNb + 1-pass GEMM -> TrTb -----
__global__ __launch_bounds__(256, 2) void k_trt_fused(const float* __restrict__ ent,
                                                      const float* __restrict__ rel,
                                                      const float* __restrict__ Wr,
                                                      const float* __restrict__ bias,
                                                      __nv_bfloat16* __restrict__ C,
                                                      int M) {
    extern __shared__ char sm[];
    uint32_t smb = smem_u32(sm);
    int tid  = threadIdx.x;
    int wid  = tid >> 5, lane = tid & 31;
    int wy   = wid >> 2, wx = wid & 3;
    int m0   = blockIdx.x * 128;
    int rows_valid = M - m0;

    // block 0 additionally normalizes the 64-row rel table (warp-per-row)
    if (blockIdx.x == 0) {
        #pragma unroll
        for (int r8 = 0; r8 < 8; r8++) {
            int row = wid * 8 + r8;
            float4 v = ((const float4*)(rel + (size_t)row * EDIM))[lane];
            float ss = v.x * v.x + v.y * v.y + v.z * v.z + v.w * v.w;
            #pragma unroll
            for (int o = 16; o; o >>= 1) ss += __shfl_xor_sync(0xffffffffu, ss, o);
            float n = sqrtf(ss);
            float s = fminf(1.0f, 1.0f / fmaxf(n, 1e-12f));
            ((float4*)(g_RelN + (size_t)row * EDIM))[lane] =
                make_float4(v.x * s, v.y * s, v.z * s, v.w * s);
        }
    }

    if (tid < 128) ((float*)(sm + OFF_BIAS))[tid] = bias[tid];

    // A prologue: raw ent rows -> maxnorm; emit scale (4B/row) + EntNb (bf16) + smem Ah
    #pragma unroll
    for (int i = 0; i < 8; i++) {
        int g = tid + i * 256;
        int row = g >> 4, c8 = g & 15, col0 = c8 * 8;
        float4 v0 = make_float4(0.f, 0.f, 0.f, 0.f), v1 = v0;
        if (row < rows_valid) {
            const float4* p = (const float4*)(ent + (size_t)(m0 + row) * EDIM) + c8 * 2;
            v0 = p[0];
            v1 = p[1];
        }
        float ss = v0.x * v0.x + v0.y * v0.y + v0.z * v0.z + v0.w * v0.w +
                   v1.x * v1.x + v1.y * v1.y + v1.z * v1.z + v1.w * v1.w;
        #pragma unroll
        for (int o = 8; o; o >>= 1) ss += __shfl_xor_sync(0xffffffffu, ss, o);
        float n = sqrtf(ss);
        float s = fminf(1.0f, 1.0f / fmaxf(n, 1e-12f));
        if (row < rows_valid && c8 == 0) g_Scale[m0 + row] = s;
        float f[8] = {v0.x * s, v0.y * s, v0.z * s, v0.w * s,
                      v1.x * s, v1.y * s, v1.z * s, v1.w * s};
        __nv_bfloat16 h[8];
        #pragma unroll
        for (int j = 0; j < 8; j++) h[j] = __float2bfloat16(f[j]);
        uint4 hv = make_uint4(pk_bf2(h[0], h[1]), pk_bf2(h[2], h[3]),
                              pk_bf2(h[4], h[5]), pk_bf2(h[6], h[7]));
        if (row < rows_valid)
            *(uint4*)(g_EntNb + (size_t)(m0 + row) * EDIM + col0) = hv;
        *(uint4*)(sm + OFF_AH + (size_t)row * LDT * 2 + col0 * 2) = hv;
    }

    load_hi(Wr, sm, OFF_BH1, tid);
    __syncthreads();

    int rowA  = wy * 64 + (lane & 15);
    int colA  = (lane >> 4) * 8;
    int nrow  = wx * 32 + (lane & 7) + ((lane >> 4) ? 8 : 0);
    int kaddB = ((lane >> 3) & 1) * 8;

    uint32_t aB = smb + OFF_AH, bB = smb + OFF_BH1;

    float d[4][4][4];
    #pragma unroll
    for (int i = 0; i < 4; i++)
        #pragma unroll
        for (int j = 0; j < 4; j++)
            #pragma unroll
            for (int q = 0; q < 4; q++) d[i][j][q] = 0.f;

    #pragma unroll
    for (int ks = 0; ks < 8; ks++) {
        int k0 = ks * 16;
        uint32_t a[4][4];
        #pragma unroll
        for (int mi = 0; mi < 4; mi++) {
            uint32_t addr = aB + (uint32_t)(((rowA + mi * 16) * LDT + k0 + colA) * 2);
            ldmx4(a[mi][0], a[mi][1], a[mi][2], a[mi][3], addr);
        }
        uint32_t b[4][2];
        #pragma unroll
        for (int nj2 = 0; nj2 < 2; nj2++) {
            uint32_t addr = bB + (uint32_t)(((nrow + nj2 * 16) * LDT + k0 + kaddB) * 2);
            uint32_t r0, r1, r2, r3;
            ldmx4(r0, r1, r2, r3, addr);
            b[nj2 * 2 + 0][0] = r0; b[nj2 * 2 + 0][1] = r1;
            b[nj2 * 2 + 1][0] = r2; b[nj2 * 2 + 1][1] = r3;
        }
        #pragma unroll
        for (int mi = 0; mi < 4; mi++)
            #pragma unroll
            for (int nj = 0; nj < 4; nj++)
                mma_bf16(d[mi][nj], a[mi], b[nj]);
    }

    const float* sb = (const float*)(sm + OFF_BIAS);
    int qrow = lane >> 2, qcol = (lane & 3) * 2;
    #pragma unroll
    for (int mi = 0; mi < 4; mi++) {
        #pragma unroll
        for (int half = 0; half < 2; half++) {
            int gm = m0 + wy * 64 + mi * 16 + qrow + half * 8;
            if (gm < M) {
                #pragma unroll
                for (int nj = 0; nj < 4; nj++) {
                    int gc = wx * 32 + nj * 8 + qcol;
                    float x0 = d[mi][nj][half * 2 + 0] + sb[gc];
                    float x1 = d[mi][nj][half * 2 + 1] + sb[gc + 1];
                    *(uint32_t*)(C + (size_t)gm * 128 + gc) =
                        pk_bf2(__float2bfloat16(x0), __float2bfloat16(x1));
                }
            }
        }
    }
}

// ---------------- k_main: attention; EntNb prefetched via cp.async -------------------
__global__ __launch_bounds__(128) void k_main(const int* __restrict__ idx,
                                              const int* __restrict__ adj_ent,
                                              const int* __restrict__ adj_rel,
                                              const float* __restrict__ ent) {
    __shared__ __align__(16) __nv_bfloat16 s_t[KNBR][EDIM];   // prefetched EntNb rows (8KB)
    __shared__ __align__(16) float s_hr[128];
    __shared__ __align__(16) float s_h[128];
    __shared__ float s_sc[32];
    __shared__ float s_att[32];
    __shared__ int   s_eid[32];
    __shared__ int   s_rid[32];

    int b   = blockIdx.x;
    int tid = threadIdx.x;

    int ib = idx[b];
    ib = min(max(ib, 0), N_ENTS - 1);

    if (tid < 32) {
        int e = adj_ent[(size_t)ib * KNBR + tid];
        s_eid[tid] = min(max(e, 0), N_ENTS - 1);
        int r = adj_rel[(size_t)ib * KNBR + tid];
        s_rid[tid] = min(max(r, 0), N_RELS - 1);
    }
    float s_ib = g_Scale[ib];   // broadcast load
    s_hr[tid] = __bfloat162float(g_TrTb[(size_t)ib * EDIM + tid]);
    s_h[tid]  = ent[(size_t)ib * EDIM + tid] * s_ib;   // h in full fp32
    __syncthreads();

    // prefetch all 32 EntNb neighbor rows into smem; retires behind the score phase
    uint32_t st_base = smem_u32(&s_t[0][0]);
    #pragma unroll
    for (int i = 0; i < 4; i++) {
        int c = tid + i * 128;          // chunk id: 32 rows x 16 chunks of 16B
        int row = c >> 4, c16 = c & 15;
        cp16(st_base + row * (EDIM * 2) + c16 * 16,
             g_EntNb + (size_t)s_eid[row] * EDIM + c16 * 8);
    }
    CP_COMMIT();

    int w = tid >> 5, l = tid & 31;
    float4 hr4 = *(const float4*)(s_hr + l * 4);

    #pragma unroll
    for (int kk = 0; kk < 8; kk++) {
        int k = w * 8 + kk;
        int e = s_eid[k], r = s_rid[k];
        uint2 trb = *(const uint2*)(g_TrTb + (size_t)e * EDIM + l * 4);
        float2 t01 = __bfloat1622float2(*(const __nv_bfloat162*)&trb.x);
        float2 t23 = __bfloat1622float2(*(const __nv_bfloat162*)&trb.y);
        float4 rv = *(const float4*)(g_RelN + (size_t)r * EDIM + l * 4);
        float p = tanh_hw(hr4.x + rv.x) * t01.x + tanh_hw(hr4.y + rv.y) * t01.y +
                  tanh_hw(hr4.z + rv.z) * t23.x + tanh_hw(hr4.w + rv.w) * t23.y;
        #pragma unroll
        for (int o = 16; o; o >>= 1) p += __shfl_xor_sync(0xffffffffu, p, o);
        if (l == 0) s_sc[k] = p;
    }
    __syncthreads();

    if (tid < 32) {
        float sc = s_sc[tid];
        float mx = sc;
        #pragma unroll
        for (int o = 16; o; o >>= 1) mx = fmaxf(mx, __shfl_xor_sync(0xffffffffu, mx, o));
        float ex = __expf(sc - mx);
        float sum = ex;
        #pragma unroll
        for (int o = 16; o; o >>= 1) sum += __shfl_xor_sync(0xffffffffu, sum, o);
        s_att[tid] = ex / sum;
    }
    CP_WAIT(0);
    __syncthreads();

    // Nh from the prefetched smem tile
    float acc = 0.f;
    #pragma unroll
    for (int k = 0; k < KNBR; k++)
        acc = fmaf(s_att[k], __bfloat162float(s_t[k][tid]), acc);

    float hv = s_h[tid];
    float x1 = hv + acc, x2 = hv * acc;
    size_t o = (size_t)b * EDIM + tid;
    __nv_bfloat16 h1 = __float2bfloat16(x1);
    g_X1h[o] = h1;
    g_X1l[o] = __float2bfloat16(x1 - __bfloat162float(h1));
    __nv_bfloat16 h2 = __float2bfloat16(x2);
    g_X2h[o] = h2;
    g_X2l[o] = __float2bfloat16(x2 - __bfloat162float(h2));
}

// ------- fused output with cp.async pipeline (round-11/13 proven) --------------------
__device__ __forceinline__ void gemm_half(uint32_t smb, int aHoff, int aLoff,
                                          int bHoff, int bLoff,
                                          int rowA, int colA, int nrow, int kaddB,
                                          float d[2][4][4]) {
    #pragma unroll
    for (int ks = 0; ks < 8; ks++) {
        int k0 = ks * 16;
        #pragma unroll
        for (int pass = 0; pass < 3; pass++) {
            uint32_t aB = smb + ((pass == 2) ? aLoff : aHoff);
            uint32_t bB = smb + ((pass == 1) ? bLoff : bHoff);
            uint32_t a[2][4];
            #pragma unroll
            for (int mi = 0; mi < 2; mi++) {
                uint32_t addr = aB + (uint32_t)(((rowA + mi * 16) * LDT + k0 + colA) * 2);
                ldmx4(a[mi][0], a[mi][1], a[mi][2], a[mi][3], addr);
            }
            uint32_t b[4][2];
            #pragma unroll
            for (int nj2 = 0; nj2 < 2; nj2++) {
                uint32_t addr = bB + (uint32_t)(((nrow + nj2 * 16) * LDT + k0 + kaddB) * 2);
                uint32_t r0, r1, r2, r3;
                ldmx4(r0, r1, r2, r3, addr);
                b[nj2 * 2 + 0][0] = r0; b[nj2 * 2 + 0][1] = r1;
                b[nj2 * 2 + 1][0] = r2; b[nj2 * 2 + 1][1] = r3;
            }
            #pragma unroll
            for (int mi = 0; mi < 2; mi++)
                #pragma unroll
                for (int nj = 0; nj < 4; nj++)
                    mma_bf16(d[mi][nj], a[mi], b[nj]);
        }
    }
}

__global__ __launch_bounds__(256, 1) void k_out_fused(const float* __restrict__ W1,
                                                      const float* __restrict__ b1,
                                                      const float* __restrict__ W2,
                                                      const float* __restrict__ b2,
                                                      float* __restrict__ C, int M) {
    extern __shared__ char sm[];
    uint32_t smb = smem_u32(sm);
    int tid  = threadIdx.x;
    int wid  = tid >> 5, lane = tid & 31;
    int wy   = wid >> 1, wx = wid & 1;
    int m0   = blockIdx.x * 128;
    int n0   = blockIdx.y * 64;

    size_t aoff = (size_t)m0 * EDIM;
    copy128_async(g_X1h + aoff, smb, OA1H, tid);
    copy128_async(g_X1l + aoff, smb, OA1L, tid);
    CP_COMMIT();
    copy128_async(g_X2h + aoff, smb, OA2H, tid);
    copy128_async(g_X2l + aoff, smb, OA2L, tid);
    CP_COMMIT();

    if (tid < 64) {
        ((float*)(sm + OFF_B1))[tid] = b1[n0 + tid];
        ((float*)(sm + OFF_B2))[tid] = b2[n0 + tid];
    }
    load_split64(W1 + (size_t)n0 * EDIM, sm, OW1H, OW1L, tid);
    load_split64(W2 + (size_t)n0 * EDIM, sm, OW2H, OW2L, tid);

    int rowA  = wy * 32 + (lane & 15);
    int colA  = (lane >> 4) * 8;
    int nrow  = wx * 32 + (lane & 7) + ((lane >> 4) ? 8 : 0);
    int kaddB = ((lane >> 3) & 1) * 8;

    float d1[2][4][4], d2[2][4][4];
    #pragma unroll
    for (int i = 0; i < 2; i++)
        #pragma unroll
        for (int j = 0; j < 4; j++)
            #pragma unroll
            for (int q = 0; q < 4; q++) { d1[i][j][q] = 0.f; d2[i][j][q] = 0.f; }

    CP_WAIT(1);
    __syncthreads();
    gemm_half(smb, OA1H, OA1L, OW1H, OW1L, rowA, colA, nrow, kaddB, d1);

    CP_WAIT(0);
    __syncthreads();
    gemm_half(smb, OA2H, OA2L, OW2H, OW2L, rowA, colA, nrow, kaddB, d2);

    const float* sb1 = (const float*)(sm + OFF_B1);
    const float* sb2 = (const float*)(sm + OFF_B2);
    int qrow = lane >> 2, qcol = (lane & 3) * 2;
    #pragma unroll
    for (int mi = 0; mi < 2; mi++) {
        #pragma unroll
        for (int half = 0; half < 2; half++) {
            int gm = m0 + wy * 32 + mi * 16 + qrow + half * 8;
            #pragma unroll
            for (int nj = 0; nj < 4; nj++) {
                int gc = wx * 32 + nj * 8 + qcol;
                float u0 = d1[mi][nj][half * 2 + 0] + sb1[gc];
                float u1 = d1[mi][nj][half * 2 + 1] + sb1[gc + 1];
                float v0 = d2[mi][nj][half * 2 + 0] + sb2[gc];
                float v1 = d2[mi][nj][half * 2 + 1] + sb2[gc + 1];
                u0 = (u0 > 0.f) ? u0 : 0.2f * u0;
                u1 = (u1 > 0.f) ? u1 : 0.2f * u1;
                v0 = (v0 > 0.f) ? v0 : 0.2f * v0;
                v1 = (v1 > 0.f) ? v1 : 0.2f * v1;
                *(float2*)(C + (size_t)gm * 128 + n0 + gc) = make_float2(u0 + v0, u1 + v1);
            }
        }
    }
}

// ---------------- launch ---------------------------------------------------------------
extern "C" void kernel_launch(void* const* d_in, const int* in_sizes, int n_in,
                              void* d_out, int out_size) {
    const int*   idx     = (const int*)d_in[0];
    const int*   adj_ent = (const int*)d_in[1];
    const int*   adj_rel = (const int*)d_in[2];
    const float* ent     = (const float*)d_in[3];
    const float* rel     = (const float*)d_in[4];
    const float* Wr_w    = (const float*)d_in[5];
    const float* Wr_b    = (const float*)d_in[6];
    const float* W1_w    = (const float*)d_in[7];
    const float* W1_b    = (const float*)d_in[8];
    const float* W2_w    = (const float*)d_in[9];
    const float* W2_b    = (const float*)d_in[10];
    float* out = (float*)d_out;

    cudaFuncSetAttribute(k_trt_fused, cudaFuncAttributeMaxDynamicSharedMemorySize, SMEM_TRT);
    cudaFuncSetAttribute(k_out_fused, cudaFuncAttributeMaxDynamicSharedMemorySize, SMEM_OUT);

    __nv_bfloat16* TrTb;
    cudaGetSymbolAddress((void**)&TrTb, g_TrTb);

    k_trt_fused<<<(N_ENTS + 127) / 128, 256, SMEM_TRT>>>(ent, rel, Wr_w, Wr_b, TrTb, N_ENTS);
    k_main<<<BATCH, 128>>>(idx, adj_ent, adj_rel, ent);
    dim3 go(BATCH / 128, 2);
    k_out_fused<<<go, 256, SMEM_OUT>>>(W1_w, W1_b, W2_w, W2_b, out, BATCH);
}